// round 1
// baseline (speedup 1.0000x reference)
#include <cuda_runtime.h>
#include <cuda_bf16.h>
#include <mma.h>
#include <cstdint>
#include <cstdio>

using namespace nvcuda;

#define E_DIM 256
#define HW    4096
#define BS    32
#define NTOK  27
#define FFD   2048
#define ST    128          // s-rows per phase-A block
#define NBLK_A 1024        // (4096/128) * 32

// ---------------- device scratch (no allocations allowed) ----------------
__device__ __nv_bfloat16 g_wk_bf[E_DIM * E_DIM];
__device__ __nv_bfloat16 g_wv_bf[E_DIM * E_DIM];
__device__ float g_Ps1[NBLK_A * E_DIM];
__device__ float g_Ps2[NBLK_A * E_DIM];
__device__ float g_ctx[E_DIM];
__device__ float g_QP[NTOK * E_DIM];
__device__ float g_KP[NTOK * E_DIM];
__device__ float g_VP[NTOK * E_DIM];
__device__ float g_Fk[NTOK * E_DIM];
__device__ float g_attout[NTOK * E_DIM];
__device__ float g_h1[NTOK * FFD];
__device__ float g_ff[NTOK * E_DIM];

// ---------------- helpers ----------------
__device__ __forceinline__ float blkSum(float v) {
    __shared__ float sh[8];
    int lane = threadIdx.x & 31, w = threadIdx.x >> 5;
#pragma unroll
    for (int o = 16; o > 0; o >>= 1) v += __shfl_xor_sync(0xffffffffu, v, o);
    __syncthreads();
    if (lane == 0) sh[w] = v;
    __syncthreads();
    float r = sh[lane & 7];
#pragma unroll
    for (int o = 4; o > 0; o >>= 1) r += __shfl_xor_sync(0xffffffffu, r, o);
    return r;
}

__device__ __forceinline__ float blkMax(float v) {
    __shared__ float sh2[8];
    int lane = threadIdx.x & 31, w = threadIdx.x >> 5;
#pragma unroll
    for (int o = 16; o > 0; o >>= 1) v = fmaxf(v, __shfl_xor_sync(0xffffffffu, v, o));
    __syncthreads();
    if (lane == 0) sh2[w] = v;
    __syncthreads();
    float r = sh2[lane & 7];
#pragma unroll
    for (int o = 4; o > 0; o >>= 1) r = fmaxf(r, __shfl_xor_sync(0xffffffffu, r, o));
    return r;
}

__device__ __forceinline__ float gelu_exact(float v) {
    return 0.5f * v * (1.0f + erff(v * 0.7071067811865475f));
}

// ---------------- prep: weight conversion, QP pos-enc, MHA k/v, F_k init ----------------
__global__ void kPrep(const float* __restrict__ shape_map,
                      const float* __restrict__ mha_wk, const float* __restrict__ mha_bk,
                      const float* __restrict__ mha_wv, const float* __restrict__ mha_bv,
                      const float* __restrict__ la_wk, const float* __restrict__ la_wv) {
    int blk = blockIdx.x, t = threadIdx.x;
    if (blk < NTOK) {
        __shared__ float x[E_DIM];
        float f = shape_map[blk * E_DIM + t];
        x[t] = f;
        g_Fk[blk * E_DIM + t] = f;
        __syncthreads();
        float ak = mha_bk[t], av = mha_bv[t];
        for (int e = 0; e < E_DIM; e++) {
            float xe = x[e];
            ak += xe * mha_wk[e * E_DIM + t];
            av += xe * mha_wv[e * E_DIM + t];
        }
        g_KP[blk * E_DIM + t] = ak;
        g_VP[blk * E_DIM + t] = av;
    } else if (blk == NTOK) {
        // query positional encoding for 3x3 grid, tiled over 3 objects
        for (int n = 0; n < NTOK; n++) {
            int j = n % 9;
            float pos = (t < 128) ? (float)(j / 3 + 1) : (float)(j % 3 + 1);
            int k = (t & 127) >> 1;
            float arg = pos / powf(10000.0f, (float)k / 64.0f);
            g_QP[n * E_DIM + t] = (t & 1) ? cosf(arg) : sinf(arg);
        }
    } else {
        int i = (blk - NTOK - 1) * 256 + t;
        if (i < E_DIM * E_DIM) {
            g_wk_bf[i] = __float2bfloat16(la_wk[i]);
            g_wv_bf[i] = __float2bfloat16(la_wv[i]);
        }
    }
}

// ---------------- Phase A: S1/S2 column sums via bf16 WMMA ----------------
#define A_LD 144
#define W_LD 48
#define C_LD 40
#define SM_A1 0
#define SM_A2 73728
#define SM_W  147456
#define SM_C  172032
#define SM_D  192512
#define SM_TOT 212992

__global__ void kA(const float* __restrict__ f_e, const float* __restrict__ pos_emb) {
    extern __shared__ char sm[];
    __nv_bfloat16* A1 = (__nv_bfloat16*)(sm + SM_A1);  // [256 K][144] col-major (M=s)
    __nv_bfloat16* A2 = (__nv_bfloat16*)(sm + SM_A2);
    __nv_bfloat16* Wc = (__nv_bfloat16*)(sm + SM_W);   // [256 K][48] row-major (32 cols)
    float* Cb = (float*)(sm + SM_C);                   // l   [128][40]
    float* Db = (float*)(sm + SM_D);                   // vv  [128][40]
    __shared__ float s1s[32], s2s[32];

    const int s0 = blockIdx.x * ST;
    const int b = blockIdx.y;
    const int t = threadIdx.x, lane = t & 31, wp = t >> 5;
    const int blk = b * gridDim.x + blockIdx.x;

    // load f_e tile: memory[s,b,e] = f_e[b,e,s]; coalesced along s
    for (int e = wp; e < E_DIM; e += 8) {
        const float4 v = ((const float4*)(f_e + ((size_t)b * E_DIM + e) * HW + s0))[lane];
        __nv_bfloat16* d2 = A2 + e * A_LD + lane * 4;
        __nv_bfloat16* d1 = A1 + e * A_LD + lane * 4;
        __nv_bfloat16 b0 = __float2bfloat16(v.x), b1 = __float2bfloat16(v.y);
        __nv_bfloat16 b2 = __float2bfloat16(v.z), b3 = __float2bfloat16(v.w);
        d2[0] = b0; d2[1] = b1; d2[2] = b2; d2[3] = b3;
        d1[0] = b0; d1[1] = b1; d1[2] = b2; d1[3] = b3;
    }
    __syncthreads();
    // add pos_emb into A1 (row (s*32+b) contiguous over e)
    for (int si = wp; si < ST; si += 8) {
        const float4* prow = (const float4*)(pos_emb + ((size_t)(s0 + si) * BS + b) * E_DIM);
        float4 p0 = prow[lane * 2], p1 = prow[lane * 2 + 1];
        float pv[8] = {p0.x, p0.y, p0.z, p0.w, p1.x, p1.y, p1.z, p1.w};
#pragma unroll
        for (int q = 0; q < 8; q++) {
            int idx = (lane * 8 + q) * A_LD + si;
            A1[idx] = __float2bfloat16(__bfloat162float(A1[idx]) + pv[q]);
        }
    }
    __syncthreads();

    for (int ch = 0; ch < 8; ch++) {
        const int c0 = ch * 32;
        // ---- Wk chunk ----
        {
            const uint4* src = (const uint4*)(g_wk_bf + t * E_DIM + c0);
            uint4* dst = (uint4*)(Wc + t * W_LD);
            dst[0] = src[0]; dst[1] = src[1]; dst[2] = src[2]; dst[3] = src[3];
        }
        __syncthreads();
        {
            wmma::fragment<wmma::matrix_a, 16, 16, 16, __nv_bfloat16, wmma::col_major> af;
            wmma::fragment<wmma::matrix_b, 16, 16, 16, __nv_bfloat16, wmma::row_major> bfr;
            wmma::fragment<wmma::accumulator, 16, 16, 16, float> acc0, acc1;
            wmma::fill_fragment(acc0, 0.0f);
            wmma::fill_fragment(acc1, 0.0f);
            for (int kk = 0; kk < E_DIM; kk += 16) {
                wmma::load_matrix_sync(af, A1 + kk * A_LD + wp * 16, A_LD);
                wmma::load_matrix_sync(bfr, Wc + kk * W_LD, W_LD);
                wmma::mma_sync(acc0, af, bfr, acc0);
                wmma::load_matrix_sync(bfr, Wc + kk * W_LD + 16, W_LD);
                wmma::mma_sync(acc1, af, bfr, acc1);
            }
            wmma::store_matrix_sync(Cb + wp * 16 * C_LD, acc0, C_LD, wmma::mem_row_major);
            wmma::store_matrix_sync(Cb + wp * 16 * C_LD + 16, acc1, C_LD, wmma::mem_row_major);
        }
        __syncthreads();
        // ---- Wv chunk ----
        {
            const uint4* src = (const uint4*)(g_wv_bf + t * E_DIM + c0);
            uint4* dst = (uint4*)(Wc + t * W_LD);
            dst[0] = src[0]; dst[1] = src[1]; dst[2] = src[2]; dst[3] = src[3];
        }
        __syncthreads();
        {
            wmma::fragment<wmma::matrix_a, 16, 16, 16, __nv_bfloat16, wmma::col_major> af;
            wmma::fragment<wmma::matrix_b, 16, 16, 16, __nv_bfloat16, wmma::row_major> bfr;
            wmma::fragment<wmma::accumulator, 16, 16, 16, float> acc0, acc1;
            wmma::fill_fragment(acc0, 0.0f);
            wmma::fill_fragment(acc1, 0.0f);
            for (int kk = 0; kk < E_DIM; kk += 16) {
                wmma::load_matrix_sync(af, A2 + kk * A_LD + wp * 16, A_LD);
                wmma::load_matrix_sync(bfr, Wc + kk * W_LD, W_LD);
                wmma::mma_sync(acc0, af, bfr, acc0);
                wmma::load_matrix_sync(bfr, Wc + kk * W_LD + 16, W_LD);
                wmma::mma_sync(acc1, af, bfr, acc1);
            }
            wmma::store_matrix_sync(Db + wp * 16 * C_LD, acc0, C_LD, wmma::mem_row_major);
            wmma::store_matrix_sync(Db + wp * 16 * C_LD + 16, acc1, C_LD, wmma::mem_row_major);
        }
        __syncthreads();
        // ---- exp + column sums over the 128 rows ----
        if (t < 32) { s1s[t] = 0.0f; s2s[t] = 0.0f; }
        __syncthreads();
        {
            int c = t & 31, rg = t >> 5;
            float s1p = 0.0f, s2p = 0.0f;
            for (int r = rg * 16; r < rg * 16 + 16; r++) {
                float el = __expf(Cb[r * C_LD + c]);
                s1p += el;
                s2p += el * Db[r * C_LD + c];
            }
            atomicAdd(&s1s[c], s1p);
            atomicAdd(&s2s[c], s2p);
        }
        __syncthreads();
        if (t < 32) {
            g_Ps1[blk * E_DIM + c0 + t] = s1s[t];
            g_Ps2[blk * E_DIM + c0 + t] = s2s[t];
        }
        __syncthreads();
    }
}

// ---------------- Phase B: reduce partials -> context ----------------
__global__ void kB(const float* __restrict__ la_bv) {
    int c = threadIdx.x;
    float s1 = 0.0f, s2 = 0.0f;
    for (int i = 0; i < NBLK_A; i++) {
        s1 += g_Ps1[i * E_DIM + c];
        s2 += g_Ps2[i * E_DIM + c];
    }
    g_ctx[c] = s2 / s1 + la_bv[c];   // la_bk cancels in the softmax ratio
}

// ---------------- Phase C (27 rows, batch-independent) ----------------
__global__ void kC1(const float* __restrict__ wq, const float* __restrict__ bq) {
    int h = blockIdx.x, t = threadIdx.x;
    __shared__ float X[NTOK * E_DIM];
    __shared__ float qp[NTOK * 32], kp[NTOK * 32], vp[NTOK * 32];
    __shared__ float sc[NTOK * NTOK];
    for (int n = 0; n < NTOK; n++) X[n * E_DIM + t] = g_Fk[n * E_DIM + t] + g_QP[n * E_DIM + t];
    for (int i = t; i < NTOK * 32; i += 256) {
        int s = i / 32, d = i % 32;
        kp[i] = g_KP[s * E_DIM + h * 32 + d];
        vp[i] = g_VP[s * E_DIM + h * 32 + d];
    }
    __syncthreads();
    for (int i = t; i < NTOK * 32; i += 256) {
        int n = i / 32, d = i % 32;
        float a = bq[h * 32 + d];
        for (int e = 0; e < E_DIM; e++) a += X[n * E_DIM + e] * wq[e * E_DIM + h * 32 + d];
        qp[i] = a;
    }
    __syncthreads();
    for (int i = t; i < NTOK * NTOK; i += 256) {
        int l = i / NTOK, s = i % NTOK;
        float a = 0.0f;
        for (int d = 0; d < 32; d++) a += qp[l * 32 + d] * kp[s * 32 + d];
        sc[i] = a * 0.17677669529663689f;   // 1/sqrt(32)
    }
    __syncthreads();
    if (t < NTOK) {
        float m = -1e30f;
        for (int s = 0; s < NTOK; s++) m = fmaxf(m, sc[t * NTOK + s]);
        float su = 0.0f;
        for (int s = 0; s < NTOK; s++) { float e = __expf(sc[t * NTOK + s] - m); sc[t * NTOK + s] = e; su += e; }
        float inv = 1.0f / su;
        for (int s = 0; s < NTOK; s++) sc[t * NTOK + s] *= inv;
    }
    __syncthreads();
    for (int i = t; i < NTOK * 32; i += 256) {
        int l = i / 32, d = i % 32;
        float a = 0.0f;
        for (int s = 0; s < NTOK; s++) a += sc[l * NTOK + s] * vp[s * 32 + d];
        g_attout[l * E_DIM + h * 32 + d] = a;
    }
}

__global__ void kC2(const float* __restrict__ wo, const float* __restrict__ bo,
                    const float* __restrict__ g, const float* __restrict__ bb) {
    int n = blockIdx.x, t = threadIdx.x;
    __shared__ float ao[E_DIM];
    ao[t] = g_attout[n * E_DIM + t];
    __syncthreads();
    float a = bo[t];
    for (int e = 0; e < E_DIM; e++) a += ao[e] * wo[e * E_DIM + t];
    float y = g_Fk[n * E_DIM + t] + a;
    float m = blkSum(y) * (1.0f / 256.0f);
    float d = y - m;
    float v = blkSum(d * d) * (1.0f / 256.0f);
    g_Fk[n * E_DIM + t] = d * rsqrtf(v + 1e-5f) * g[t] + bb[t];
}

__global__ void kC3(const float* __restrict__ wq, const float* __restrict__ bq,
                    const float* __restrict__ g, const float* __restrict__ bb) {
    int n = blockIdx.x, t = threadIdx.x;
    __shared__ float x[E_DIM];
    float f = g_Fk[n * E_DIM + t];
    x[t] = f + g_QP[n * E_DIM + t];
    __syncthreads();
    float a = bq[t];
    for (int e = 0; e < E_DIM; e++) a += x[e] * wq[e * E_DIM + t];
    a *= 0.0625f;   // E^-0.5
    float mx = blkMax(a);
    float e = __expf(a - mx);
    float s = blkSum(e);
    float y = f + (e / s) * g_ctx[t];
    float m = blkSum(y) * (1.0f / 256.0f);
    float d = y - m;
    float v = blkSum(d * d) * (1.0f / 256.0f);
    g_Fk[n * E_DIM + t] = d * rsqrtf(v + 1e-5f) * g[t] + bb[t];
}

__global__ void kC4(const float* __restrict__ w1, const float* __restrict__ b1) {
    int rg = blockIdx.x;                  // 0..8 (3 rows each)
    int cc = blockIdx.y * 256 + threadIdx.x;
    int t = threadIdx.x;
    __shared__ float x[3][E_DIM];
    for (int r = 0; r < 3; r++) x[r][t] = g_Fk[(rg * 3 + r) * E_DIM + t];
    __syncthreads();
    float bv = b1[cc];
    float a0 = bv, a1 = bv, a2 = bv;
    for (int e = 0; e < E_DIM; e++) {
        float w = w1[e * FFD + cc];
        a0 += x[0][e] * w; a1 += x[1][e] * w; a2 += x[2][e] * w;
    }
    g_h1[(rg * 3 + 0) * FFD + cc] = gelu_exact(a0);
    g_h1[(rg * 3 + 1) * FFD + cc] = gelu_exact(a1);
    g_h1[(rg * 3 + 2) * FFD + cc] = gelu_exact(a2);
}

__global__ void kC5a(const float* __restrict__ w2, const float* __restrict__ b2) {
    int rg = blockIdx.x;                       // 0..8
    int c = blockIdx.y * 64 + (threadIdx.x & 63);
    int rsel = threadIdx.x >> 6;               // 0..3 (3 used)
    int t = threadIdx.x;
    __shared__ float hs[3][FFD];
    for (int idx = t; idx < 3 * FFD; idx += 256)
        hs[idx / FFD][idx % FFD] = g_h1[(rg * 3 + idx / FFD) * FFD + idx % FFD];
    __syncthreads();
    if (rsel < 3) {
        const float* h = hs[rsel];
        float a0 = 0.0f, a1 = 0.0f, a2 = 0.0f, a3 = 0.0f;
        for (int j = 0; j < FFD; j += 4) {
            a0 += h[j + 0] * w2[(j + 0) * E_DIM + c];
            a1 += h[j + 1] * w2[(j + 1) * E_DIM + c];
            a2 += h[j + 2] * w2[(j + 2) * E_DIM + c];
            a3 += h[j + 3] * w2[(j + 3) * E_DIM + c];
        }
        g_ff[(rg * 3 + rsel) * E_DIM + c] = (a0 + a1) + (a2 + a3) + b2[c];
    }
}

__global__ void kC5b(const float* __restrict__ g, const float* __restrict__ bb,
                     float* __restrict__ out, int step) {
    int n = blockIdx.x, t = threadIdx.x;
    float y = g_Fk[n * E_DIM + t] + g_ff[n * E_DIM + t];
    float m = blkSum(y) * (1.0f / 256.0f);
    float d = y - m;
    float v = blkSum(d * d) * (1.0f / 256.0f);
    float r = d * rsqrtf(v + 1e-5f) * g[t] + bb[t];
    g_Fk[n * E_DIM + t] = r;
    float* o = out + ((size_t)(step * NTOK + n) * BS) * E_DIM + t;
#pragma unroll
    for (int b = 0; b < BS; b++) o[b * E_DIM] = r;
}

// ---------------- launch ----------------
extern "C" void kernel_launch(void* const* d_in, const int* in_sizes, int n_in,
                              void* d_out, int out_size) {
    const float* f_e      = (const float*)d_in[0];
    const float* pos_emb  = (const float*)d_in[1];
    // d_in[2] = bboxes (unused by the forward pass)
    const float* shape_map= (const float*)d_in[3];
    const float* mha_wq   = (const float*)d_in[4];
    const float* mha_bq   = (const float*)d_in[5];
    const float* mha_wk   = (const float*)d_in[6];
    const float* mha_bk   = (const float*)d_in[7];
    const float* mha_wv   = (const float*)d_in[8];
    const float* mha_bv   = (const float*)d_in[9];
    const float* mha_wo   = (const float*)d_in[10];
    const float* mha_bo   = (const float*)d_in[11];
    const float* la_wq    = (const float*)d_in[12];
    const float* la_bq    = (const float*)d_in[13];
    const float* la_wk    = (const float*)d_in[14];
    const float* la_bk    = (const float*)d_in[15]; (void)la_bk; // cancels in softmax ratio
    const float* la_wv    = (const float*)d_in[16];
    const float* la_bv    = (const float*)d_in[17];
    const float* ff_w1    = (const float*)d_in[18];
    const float* ff_b1    = (const float*)d_in[19];
    const float* ff_w2    = (const float*)d_in[20];
    const float* ff_b2    = (const float*)d_in[21];
    const float* n1_g     = (const float*)d_in[22];
    const float* n1_b     = (const float*)d_in[23];
    const float* n2_g     = (const float*)d_in[24];
    const float* n2_b     = (const float*)d_in[25];
    const float* n3_g     = (const float*)d_in[26];
    const float* n3_b     = (const float*)d_in[27];
    float* out = (float*)d_out;

    cudaFuncSetAttribute(kA, cudaFuncAttributeMaxDynamicSharedMemorySize, SM_TOT);

    kPrep<<<NTOK + 1 + 256, 256>>>(shape_map, mha_wk, mha_bk, mha_wv, mha_bv, la_wk, la_wv);
    kA<<<dim3(HW / ST, BS), 256, SM_TOT>>>(f_e, pos_emb);
    kB<<<1, 256>>>(la_bv);
    for (int step = 0; step < 3; step++) {
        kC1<<<8, 256>>>(mha_wq, mha_bq);
        kC2<<<NTOK, 256>>>(mha_wo, mha_bo, n1_g, n1_b);
        kC3<<<NTOK, 256>>>(la_wq, la_bq, n2_g, n2_b);
        kC4<<<dim3(9, 8), 256>>>(ff_w1, ff_b1);
        kC5a<<<dim3(9, 4), 256>>>(ff_w2, ff_b2);
        kC5b<<<NTOK, 256>>>(n3_g, n3_b, out, step);
    }
}

// round 2
// speedup vs baseline: 1.5910x; 1.5910x over previous
#include <cuda_runtime.h>
#include <cuda_bf16.h>
#include <mma.h>
#include <cstdint>

using namespace nvcuda;

#define E_DIM 256
#define HW    4096
#define BS    32
#define NTOK  27
#define FFD   2048
#define ST    128
#define NBLK_A 1024                 // (4096/128) * 32
#define NPART (NBLK_A * 8)          // per-warp partials, 8192

// ---------------- device scratch ----------------
__device__ __nv_bfloat16 g_wk_bf[E_DIM * E_DIM];
__device__ __nv_bfloat16 g_wv_bf[E_DIM * E_DIM];
__device__ __nv_bfloat16 g_posT[(size_t)BS * E_DIM * HW];   // [b][e][s] bf16
__device__ float g_Ps1[E_DIM * NPART];                      // [c][part]
__device__ float g_Ps2[E_DIM * NPART];
__device__ float g_ctx[E_DIM];
__device__ float g_QP[NTOK * E_DIM];
__device__ float g_KP[NTOK * E_DIM];
__device__ float g_VP[NTOK * E_DIM];
__device__ float g_Fk[NTOK * E_DIM];
__device__ float g_h1[NTOK * FFD];
__device__ float g_ffp[4 * NTOK * E_DIM];

// ---------------- helpers ----------------
__device__ __forceinline__ float blkSum(float v) {
    __shared__ float sh[8];
    int lane = threadIdx.x & 31, w = threadIdx.x >> 5;
#pragma unroll
    for (int o = 16; o > 0; o >>= 1) v += __shfl_xor_sync(0xffffffffu, v, o);
    __syncthreads();
    if (lane == 0) sh[w] = v;
    __syncthreads();
    float r = sh[lane & 7];
#pragma unroll
    for (int o = 4; o > 0; o >>= 1) r += __shfl_xor_sync(0xffffffffu, r, o);
    return r;
}

__device__ __forceinline__ float blkMax(float v) {
    __shared__ float sh2[8];
    int lane = threadIdx.x & 31, w = threadIdx.x >> 5;
#pragma unroll
    for (int o = 16; o > 0; o >>= 1) v = fmaxf(v, __shfl_xor_sync(0xffffffffu, v, o));
    __syncthreads();
    if (lane == 0) sh2[w] = v;
    __syncthreads();
    float r = sh2[lane & 7];
#pragma unroll
    for (int o = 4; o > 0; o >>= 1) r = fmaxf(r, __shfl_xor_sync(0xffffffffu, r, o));
    return r;
}

__device__ __forceinline__ float gelu_exact(float v) {
    return 0.5f * v * (1.0f + erff(v * 0.7071067811865475f));
}

// ---------------- prep: weights -> bf16, QP pos-enc, MHA k/v proj, F_k init ----------------
__global__ void kPrep(const float* __restrict__ shape_map,
                      const float* __restrict__ mha_wk, const float* __restrict__ mha_bk,
                      const float* __restrict__ mha_wv, const float* __restrict__ mha_bv,
                      const float* __restrict__ la_wk, const float* __restrict__ la_wv) {
    int blk = blockIdx.x, t = threadIdx.x;
    if (blk < NTOK) {
        __shared__ float x[E_DIM];
        float f = shape_map[blk * E_DIM + t];
        x[t] = f;
        g_Fk[blk * E_DIM + t] = f;
        __syncthreads();
        float ak = mha_bk[t], av = mha_bv[t];
#pragma unroll 4
        for (int e = 0; e < E_DIM; e++) {
            float xe = x[e];
            ak += xe * mha_wk[e * E_DIM + t];
            av += xe * mha_wv[e * E_DIM + t];
        }
        g_KP[blk * E_DIM + t] = ak;
        g_VP[blk * E_DIM + t] = av;
    } else if (blk == NTOK) {
        for (int n = 0; n < NTOK; n++) {
            int j = n % 9;
            float pos = (t < 128) ? (float)(j / 3 + 1) : (float)(j % 3 + 1);
            int k = (t & 127) >> 1;
            float arg = pos / powf(10000.0f, (float)k / 64.0f);
            g_QP[n * E_DIM + t] = (t & 1) ? cosf(arg) : sinf(arg);
        }
    } else {
        int i = (blk - NTOK - 1) * 256 + t;
        if (i < E_DIM * E_DIM) {
            g_wk_bf[i] = __float2bfloat16(la_wk[i]);
            g_wv_bf[i] = __float2bfloat16(la_wv[i]);
        }
    }
}

// ---------------- kT: transpose pos_emb [s][b][e] fp32 -> posT [b][e][s] bf16 ----------------
__global__ void kT(const float* __restrict__ pos) {
    // grid (32 s-blocks, 4 e-blocks, 32 b), 256 threads = 8 warps, warp = 32x32 subtile
    __shared__ float tile[8][32][33];
    int wp = threadIdx.x >> 5, lane = threadIdx.x & 31;
    int ssub = wp & 3, esub = wp >> 2;
    int s0 = blockIdx.x * 128 + ssub * 32;
    int e0 = blockIdx.y * 64 + esub * 32;
    int b = blockIdx.z;
    float(*tl)[33] = tile[wp];
#pragma unroll
    for (int i = 0; i < 8; i++) {
        int si = i * 4 + (lane >> 3);
        int e = (lane & 7) * 4;
        const float4 v = *(const float4*)(pos + ((size_t)(s0 + si) * BS + b) * E_DIM + e0 + e);
        tl[si][e] = v.x; tl[si][e + 1] = v.y; tl[si][e + 2] = v.z; tl[si][e + 3] = v.w;
    }
    __syncwarp();
#pragma unroll
    for (int i = 0; i < 16; i++) {
        int e = i * 2 + (lane >> 4);
        int s = (lane & 15) * 2;
        __nv_bfloat162 p = __floats2bfloat162_rn(tl[s][e], tl[s + 1][e]);
        *(__nv_bfloat162*)(g_posT + ((size_t)b * E_DIM + e0 + e) * HW + s0 + s) = p;
    }
}

// ---------------- Phase A: column sums of exp(L)*VV via bf16 WMMA ----------------
#define A_LD 136
#define W_LD 40
#define C_LD 36
#define SM_A1 0
#define SM_A2 69632
#define SM_WK 139264
#define SM_WV 159744
#define SM_C  180224
#define SM_D  198656
#define SM_TOT_A 217088

__global__ void kA(const float* __restrict__ f_e) {
    extern __shared__ char sm[];
    __nv_bfloat16* A1 = (__nv_bfloat16*)(sm + SM_A1);   // (x+p) col-major [k=e][m=s] ld A_LD
    __nv_bfloat16* A2 = (__nv_bfloat16*)(sm + SM_A2);   // x     col-major
    __nv_bfloat16* Wks = (__nv_bfloat16*)(sm + SM_WK);  // [k=e][n=32] ld W_LD
    __nv_bfloat16* Wvs = (__nv_bfloat16*)(sm + SM_WV);
    float* Cb = (float*)(sm + SM_C);                    // per-warp 16x36
    float* Db = (float*)(sm + SM_D);

    const int s0 = blockIdx.x * ST;
    const int b = blockIdx.y;
    const int t = threadIdx.x, lane = t & 31, wp = t >> 5;
    const int bid = b * gridDim.x + blockIdx.x;

    // ---- build A tiles: conflict-free, register add ----
    for (int e = wp; e < E_DIM; e += 8) {
        const float4 v = ((const float4*)(f_e + ((size_t)b * E_DIM + e) * HW + s0))[lane];
        __nv_bfloat16 pb[4];
        *(uint2*)pb = *(const uint2*)(g_posT + ((size_t)b * E_DIM + e) * HW + s0 + lane * 4);
        __nv_bfloat16 x0 = __float2bfloat16(v.x), x1 = __float2bfloat16(v.y);
        __nv_bfloat16 x2 = __float2bfloat16(v.z), x3 = __float2bfloat16(v.w);
        __nv_bfloat16 a0 = __float2bfloat16(v.x + __bfloat162float(pb[0]));
        __nv_bfloat16 a1 = __float2bfloat16(v.y + __bfloat162float(pb[1]));
        __nv_bfloat16 a2 = __float2bfloat16(v.z + __bfloat162float(pb[2]));
        __nv_bfloat16 a3 = __float2bfloat16(v.w + __bfloat162float(pb[3]));
        __nv_bfloat16 tmp2[4] = {x0, x1, x2, x3};
        __nv_bfloat16 tmp1[4] = {a0, a1, a2, a3};
        *(uint2*)(A2 + e * A_LD + lane * 4) = *(uint2*)tmp2;
        *(uint2*)(A1 + e * A_LD + lane * 4) = *(uint2*)tmp1;
    }

    float* Cw = Cb + wp * 16 * C_LD;
    float* Dw = Db + wp * 16 * C_LD;

    for (int ch = 0; ch < 8; ch++) {
        const int c0 = ch * 32;
        __syncthreads();
        // copy W chunks (32 cols of Wk and Wv), thread t = e-row
        {
            const uint4* sk = (const uint4*)(g_wk_bf + t * E_DIM + c0);
            const uint4* sv = (const uint4*)(g_wv_bf + t * E_DIM + c0);
            uint4* dk = (uint4*)(Wks + t * W_LD);
            uint4* dv = (uint4*)(Wvs + t * W_LD);
            dk[0] = sk[0]; dk[1] = sk[1]; dk[2] = sk[2]; dk[3] = sk[3];
            dv[0] = sv[0]; dv[1] = sv[1]; dv[2] = sv[2]; dv[3] = sv[3];
        }
        __syncthreads();

        wmma::fragment<wmma::matrix_a, 16, 16, 16, __nv_bfloat16, wmma::col_major> a1f, a2f;
        wmma::fragment<wmma::matrix_b, 16, 16, 16, __nv_bfloat16, wmma::row_major> bk0, bk1, bv0, bv1;
        wmma::fragment<wmma::accumulator, 16, 16, 16, float> ck0, ck1, cv0, cv1;
        wmma::fill_fragment(ck0, 0.0f); wmma::fill_fragment(ck1, 0.0f);
        wmma::fill_fragment(cv0, 0.0f); wmma::fill_fragment(cv1, 0.0f);
#pragma unroll
        for (int k0 = 0; k0 < E_DIM; k0 += 16) {
            wmma::load_matrix_sync(a1f, A1 + k0 * A_LD + wp * 16, A_LD);
            wmma::load_matrix_sync(bk0, Wks + k0 * W_LD, W_LD);
            wmma::load_matrix_sync(bk1, Wks + k0 * W_LD + 16, W_LD);
            wmma::mma_sync(ck0, a1f, bk0, ck0);
            wmma::mma_sync(ck1, a1f, bk1, ck1);
            wmma::load_matrix_sync(a2f, A2 + k0 * A_LD + wp * 16, A_LD);
            wmma::load_matrix_sync(bv0, Wvs + k0 * W_LD, W_LD);
            wmma::load_matrix_sync(bv1, Wvs + k0 * W_LD + 16, W_LD);
            wmma::mma_sync(cv0, a2f, bv0, cv0);
            wmma::mma_sync(cv1, a2f, bv1, cv1);
        }
        // warp-private epilogue
        wmma::store_matrix_sync(Cw, ck0, C_LD, wmma::mem_row_major);
        wmma::store_matrix_sync(Cw + 16, ck1, C_LD, wmma::mem_row_major);
        wmma::store_matrix_sync(Dw, cv0, C_LD, wmma::mem_row_major);
        wmma::store_matrix_sync(Dw + 16, cv1, C_LD, wmma::mem_row_major);
        __syncwarp();
        float s1p = 0.0f, s2p = 0.0f;
#pragma unroll
        for (int r = 0; r < 16; r++) {
            float el = __expf(Cw[r * C_LD + lane]);
            s1p += el;
            s2p += el * Dw[r * C_LD + lane];
        }
        g_Ps1[(size_t)(c0 + lane) * NPART + bid * 8 + wp] = s1p;
        g_Ps2[(size_t)(c0 + lane) * NPART + bid * 8 + wp] = s2p;
    }
}

// ---------------- Phase B: reduce partials -> context ----------------
__global__ void kB(const float* __restrict__ la_bv) {
    int c = blockIdx.x, t = threadIdx.x;
    float s1 = 0.0f, s2 = 0.0f;
    for (int j = 0; j < NPART / 256; j++) {
        s1 += g_Ps1[(size_t)c * NPART + j * 256 + t];
        s2 += g_Ps2[(size_t)c * NPART + j * 256 + t];
    }
    s1 = blkSum(s1);
    s2 = blkSum(s2);
    if (t == 0) g_ctx[c] = s2 / s1 + la_bv[c];  // la_bk cancels; la_bv adds post-hoc
}

// ---------------- Phase C (27 rows, batch-independent) ----------------
// fused MHA: q-proj + scores + softmax + AV + o-proj + residual + LN1
__global__ void kAtt(const float* __restrict__ wq, const float* __restrict__ bq,
                     const float* __restrict__ wo, const float* __restrict__ bo,
                     const float* __restrict__ g, const float* __restrict__ bb) {
    extern __shared__ float dsm[];
    float* X   = dsm;                 // 256
    float* q   = X + 256;             // 256
    float* KPs = q + 256;             // 27*256
    float* VPs = KPs + NTOK * 256;    // 27*256
    float* scr = VPs + NTOK * 256;    // 8*27
    float* al  = scr + 8 * NTOK;      // 8*27
    float* ao  = al + 8 * NTOK;       // 256
    int n = blockIdx.x, t = threadIdx.x;

    float f = g_Fk[n * E_DIM + t];
    X[t] = f + g_QP[n * E_DIM + t];
    for (int i = t; i < NTOK * E_DIM; i += 256) { KPs[i] = g_KP[i]; VPs[i] = g_VP[i]; }
    __syncthreads();
    // q projection
    float a = bq[t];
#pragma unroll 4
    for (int e = 0; e < E_DIM; e++) a += X[e] * wq[e * E_DIM + t];
    q[t] = a;
    __syncthreads();
    // scores
    if (t < 8 * NTOK) {
        int h = t / NTOK, s = t % NTOK;
        float sc = 0.0f;
#pragma unroll
        for (int d = 0; d < 32; d++) sc += q[h * 32 + d] * KPs[s * E_DIM + h * 32 + d];
        scr[t] = sc * 0.17677669529663689f;
    }
    __syncthreads();
    if (t < 8) {
        float m = -1e30f;
        for (int s = 0; s < NTOK; s++) m = fmaxf(m, scr[t * NTOK + s]);
        float su = 0.0f;
        for (int s = 0; s < NTOK; s++) { float e = __expf(scr[t * NTOK + s] - m); al[t * NTOK + s] = e; su += e; }
        float inv = 1.0f / su;
        for (int s = 0; s < NTOK; s++) al[t * NTOK + s] *= inv;
    }
    __syncthreads();
    // attention output
    {
        int h = t >> 5;
        float acc = 0.0f;
#pragma unroll
        for (int s = 0; s < NTOK; s++) acc += al[h * NTOK + s] * VPs[s * E_DIM + t];
        ao[t] = acc;
    }
    __syncthreads();
    // output projection + residual + LN
    float o = bo[t];
#pragma unroll 4
    for (int e = 0; e < E_DIM; e++) o += ao[e] * wo[e * E_DIM + t];
    float y = f + o;
    float m = blkSum(y) * (1.0f / 256.0f);
    float d = y - m;
    float v = blkSum(d * d) * (1.0f / 256.0f);
    g_Fk[n * E_DIM + t] = d * rsqrtf(v + 1e-5f) * g[t] + bb[t];
}

__global__ void kLA(const float* __restrict__ wq, const float* __restrict__ bq,
                    const float* __restrict__ g, const float* __restrict__ bb) {
    int n = blockIdx.x, t = threadIdx.x;
    __shared__ float x[E_DIM];
    float f = g_Fk[n * E_DIM + t];
    x[t] = f + g_QP[n * E_DIM + t];
    __syncthreads();
    float a = bq[t];
#pragma unroll 4
    for (int e = 0; e < E_DIM; e++) a += x[e] * wq[e * E_DIM + t];
    a *= 0.0625f;
    float mx = blkMax(a);
    float e1 = __expf(a - mx);
    float s = blkSum(e1);
    float y = f + (e1 / s) * g_ctx[t];
    float m = blkSum(y) * (1.0f / 256.0f);
    float d = y - m;
    float v = blkSum(d * d) * (1.0f / 256.0f);
    g_Fk[n * E_DIM + t] = d * rsqrtf(v + 1e-5f) * g[t] + bb[t];
}

__global__ void kFF1(const float* __restrict__ w1, const float* __restrict__ b1) {
    int n = blockIdx.x, c = blockIdx.y * 256 + threadIdx.x, t = threadIdx.x;
    __shared__ float x[E_DIM];
    x[t] = g_Fk[n * E_DIM + t];
    __syncthreads();
    float a = b1[c];
#pragma unroll 4
    for (int e = 0; e < E_DIM; e++) a += x[e] * w1[e * FFD + c];
    g_h1[n * FFD + c] = gelu_exact(a);
}

__global__ void kFF2(const float* __restrict__ w2) {
    int n = blockIdx.x, jb = blockIdx.y, t = threadIdx.x;
    __shared__ float h[512];
    for (int i = t; i < 512; i += 256) h[i] = g_h1[n * FFD + jb * 512 + i];
    __syncthreads();
    float a = 0.0f;
#pragma unroll 4
    for (int j = 0; j < 512; j++) a += h[j] * w2[(jb * 512 + j) * E_DIM + t];
    g_ffp[(jb * NTOK + n) * E_DIM + t] = a;
}

__global__ void kFin(const float* __restrict__ b2, const float* __restrict__ g,
                     const float* __restrict__ bb, float* __restrict__ out, int step) {
    int n = blockIdx.x, t = threadIdx.x;
    float y = g_Fk[n * E_DIM + t] + b2[t];
#pragma unroll
    for (int p = 0; p < 4; p++) y += g_ffp[(p * NTOK + n) * E_DIM + t];
    float m = blkSum(y) * (1.0f / 256.0f);
    float d = y - m;
    float v = blkSum(d * d) * (1.0f / 256.0f);
    float r = d * rsqrtf(v + 1e-5f) * g[t] + bb[t];
    g_Fk[n * E_DIM + t] = r;
    float* o = out + ((size_t)(step * NTOK + n) * BS) * E_DIM + t;
#pragma unroll
    for (int b = 0; b < BS; b++) o[b * E_DIM] = r;
}

// ---------------- launch ----------------
extern "C" void kernel_launch(void* const* d_in, const int* in_sizes, int n_in,
                              void* d_out, int out_size) {
    const float* f_e      = (const float*)d_in[0];
    const float* pos_emb  = (const float*)d_in[1];
    const float* shape_map= (const float*)d_in[3];
    const float* mha_wq   = (const float*)d_in[4];
    const float* mha_bq   = (const float*)d_in[5];
    const float* mha_wk   = (const float*)d_in[6];
    const float* mha_bk   = (const float*)d_in[7];
    const float* mha_wv   = (const float*)d_in[8];
    const float* mha_bv   = (const float*)d_in[9];
    const float* mha_wo   = (const float*)d_in[10];
    const float* mha_bo   = (const float*)d_in[11];
    const float* la_wq    = (const float*)d_in[12];
    const float* la_bq    = (const float*)d_in[13];
    const float* la_wk    = (const float*)d_in[14];
    const float* la_wv    = (const float*)d_in[16];
    const float* la_bv    = (const float*)d_in[17];
    const float* ff_w1    = (const float*)d_in[18];
    const float* ff_b1    = (const float*)d_in[19];
    const float* ff_w2    = (const float*)d_in[20];
    const float* ff_b2    = (const float*)d_in[21];
    const float* n1_g     = (const float*)d_in[22];
    const float* n1_b     = (const float*)d_in[23];
    const float* n2_g     = (const float*)d_in[24];
    const float* n2_b     = (const float*)d_in[25];
    const float* n3_g     = (const float*)d_in[26];
    const float* n3_b     = (const float*)d_in[27];
    float* out = (float*)d_out;

    static bool attr_set = false;
    if (!attr_set) {
        cudaFuncSetAttribute(kA, cudaFuncAttributeMaxDynamicSharedMemorySize, SM_TOT_A);
        cudaFuncSetAttribute(kAtt, cudaFuncAttributeMaxDynamicSharedMemorySize, 64 * 1024);
        attr_set = true;
    }
    const int att_smem = (256 + 256 + 2 * NTOK * 256 + 2 * 8 * NTOK + 256) * 4;

    kPrep<<<NTOK + 1 + 256, 256>>>(shape_map, mha_wk, mha_bk, mha_wv, mha_bv, la_wk, la_wv);
    kT<<<dim3(32, 4, 32), 256>>>(pos_emb);
    kA<<<dim3(HW / ST, BS), 256, SM_TOT_A>>>(f_e);
    kB<<<E_DIM, 256>>>(la_bv);
    for (int step = 0; step < 3; step++) {
        kAtt<<<NTOK, 256, att_smem>>>(mha_wq, mha_bq, mha_wo, mha_bo, n1_g, n1_b);
        kLA<<<NTOK, 256>>>(la_wq, la_bq, n2_g, n2_b);
        kFF1<<<dim3(NTOK, 8), 256>>>(ff_w1, ff_b1);
        kFF2<<<dim3(NTOK, 4), 256>>>(ff_w2);
        kFin<<<NTOK, 256>>>(ff_b2, n3_g, n3_b, out, step);
    }
}

// round 4
// speedup vs baseline: 2.9543x; 1.8569x over previous
#include <cuda_runtime.h>
#include <cuda_bf16.h>
#include <mma.h>
#include <cstdint>

using namespace nvcuda;

#define E_DIM 256
#define HW    4096
#define BS    32
#define NTOK  27
#define FFD   2048
#define NPARTS 1024

// ---------------- device scratch ----------------
__device__ __nv_bfloat16 g_wTk[E_DIM * E_DIM];   // Wk^T [c][e] bf16
__device__ __nv_bfloat16 g_wTv[E_DIM * E_DIM];   // Wv^T [c][e] bf16
__device__ float g_Ps1[E_DIM * NPARTS];          // [c][part]
__device__ float g_Ps2[E_DIM * NPARTS];
__device__ float g_ctx[E_DIM];
__device__ float g_QP[NTOK * E_DIM];
__device__ float g_KP[NTOK * E_DIM];
__device__ float g_VP[NTOK * E_DIM];
__device__ float g_Fk[NTOK * E_DIM];

// ---------------- helpers ----------------
// 256-thread block sum (kB)
__device__ __forceinline__ float blkSum256(float v) {
    __shared__ float sh[8];
    int lane = threadIdx.x & 31, w = threadIdx.x >> 5;
#pragma unroll
    for (int o = 16; o > 0; o >>= 1) v += __shfl_xor_sync(0xffffffffu, v, o);
    __syncthreads();
    if (lane == 0) sh[w] = v;
    __syncthreads();
    float r = sh[lane & 7];
#pragma unroll
    for (int o = 4; o > 0; o >>= 1) r += __shfl_xor_sync(0xffffffffu, r, o);
    return r;
}

// 1024-thread block reductions (kC)
__device__ __forceinline__ float bSum(float v) {
    __shared__ float sh[33];
    int lane = threadIdx.x & 31, w = threadIdx.x >> 5;
#pragma unroll
    for (int o = 16; o > 0; o >>= 1) v += __shfl_xor_sync(0xffffffffu, v, o);
    if (lane == 0) sh[w] = v;
    __syncthreads();
    if (w == 0) {
        float r = sh[lane];
#pragma unroll
        for (int o = 16; o > 0; o >>= 1) r += __shfl_xor_sync(0xffffffffu, r, o);
        if (lane == 0) sh[32] = r;
    }
    __syncthreads();
    float r = sh[32];
    __syncthreads();
    return r;
}
__device__ __forceinline__ float bMax(float v) {
    __shared__ float sh2[33];
    int lane = threadIdx.x & 31, w = threadIdx.x >> 5;
#pragma unroll
    for (int o = 16; o > 0; o >>= 1) v = fmaxf(v, __shfl_xor_sync(0xffffffffu, v, o));
    if (lane == 0) sh2[w] = v;
    __syncthreads();
    if (w == 0) {
        float r = sh2[lane];
#pragma unroll
        for (int o = 16; o > 0; o >>= 1) r = fmaxf(r, __shfl_xor_sync(0xffffffffu, r, o));
        if (lane == 0) sh2[32] = r;
    }
    __syncthreads();
    float r = sh2[32];
    __syncthreads();
    return r;
}
__device__ __forceinline__ float gelu_exact(float v) {
    return 0.5f * v * (1.0f + erff(v * 0.7071067811865475f));
}

// ---------------- kPrep ----------------
__global__ void kPrep(const float* __restrict__ shape_map,
                      const float* __restrict__ mha_wk, const float* __restrict__ mha_bk,
                      const float* __restrict__ mha_wv, const float* __restrict__ mha_bv,
                      const float* __restrict__ la_wk, const float* __restrict__ la_wv) {
    int blk = blockIdx.x, t = threadIdx.x;
    if (blk < NTOK) {
        __shared__ float x[E_DIM];
        float f = shape_map[blk * E_DIM + t];
        x[t] = f;
        g_Fk[blk * E_DIM + t] = f;
        __syncthreads();
        float ak = mha_bk[t], av = mha_bv[t];
#pragma unroll 4
        for (int e = 0; e < E_DIM; e++) {
            float xe = x[e];
            ak += xe * mha_wk[e * E_DIM + t];
            av += xe * mha_wv[e * E_DIM + t];
        }
        g_KP[blk * E_DIM + t] = ak;
        g_VP[blk * E_DIM + t] = av;
    } else if (blk == NTOK) {
        for (int n = 0; n < NTOK; n++) {
            int j = n % 9;
            float pos = (t < 128) ? (float)(j / 3 + 1) : (float)(j % 3 + 1);
            int k = (t & 127) >> 1;
            float arg = pos / powf(10000.0f, (float)k / 64.0f);
            g_QP[n * E_DIM + t] = (t & 1) ? cosf(arg) : sinf(arg);
        }
    } else {
        int i = (blk - NTOK - 1) * 256 + t;   // i = e*256 + c
        int e = i >> 8, c = i & 255;
        g_wTk[c * E_DIM + e] = __float2bfloat16(la_wk[i]);
        g_wTv[c * E_DIM + e] = __float2bfloat16(la_wv[i]);
    }
}

// ---------------- kA: Phase A (fused transpose + bf16 WMMA + exp-colsum) ----------------
// smem: A1 [0,67584), A2 [67584,135168), Wregion [135168,204800)
//   Wregion phases: (1) fp32 transpose staging 8*32*33*4 = 33792
//                   (2) W chunks: Wk 64x528=33792 @ +0, Wv @ +33792
//                   (3) C staging: per-warp 2x(16x68 f32) = 8704 B * 8 = 69632
//                   (4) per-warp col partials: 2 * 8*256*4 = 16384
#define ALD 264             // bf16 elems per row (528 B)
#define SA1 0
#define SA2 67584
#define SWR 135168
#define SMEM_KA 204800

__global__ void __launch_bounds__(256, 1) kA(const float* __restrict__ f_e,
                                             const float* __restrict__ pos) {
    extern __shared__ char sm[];
    __nv_bfloat16* A1 = (__nv_bfloat16*)(sm + SA1);
    __nv_bfloat16* A2 = (__nv_bfloat16*)(sm + SA2);

    const int t = threadIdx.x, lane = t & 31, wp = t >> 5;
    const int sblk = blockIdx.x, b = blockIdx.y;
    const int bid = b * 32 + sblk;

    // ---- fused transpose load: f_e [b][e][s] -> A2 [s][e]; A1 = A2 + pos ----
    {
        float* tl = (float*)(sm + SWR) + wp * (32 * 33);
        const float* src = f_e + ((size_t)b * E_DIM + wp * 32) * HW + (size_t)sblk * 128;
#pragma unroll
        for (int ssub = 0; ssub < 4; ssub++) {
            const float* s2 = src + ssub * 32;
#pragma unroll
            for (int i = 0; i < 32; i++) tl[i * 33 + lane] = s2[(size_t)i * HW + lane];
            __syncwarp();
            int sl = ssub * 32 + lane;
            const float* prow = pos + ((size_t)(sblk * 128 + sl) * BS + b) * E_DIM + wp * 32;
            __nv_bfloat16 r1[32], r2[32];
#pragma unroll
            for (int e8 = 0; e8 < 8; e8++) {
                float4 pv = *(const float4*)(prow + e8 * 4);
                float x0 = tl[(e8 * 4 + 0) * 33 + lane];
                float x1 = tl[(e8 * 4 + 1) * 33 + lane];
                float x2 = tl[(e8 * 4 + 2) * 33 + lane];
                float x3 = tl[(e8 * 4 + 3) * 33 + lane];
                r2[e8 * 4 + 0] = __float2bfloat16(x0);
                r2[e8 * 4 + 1] = __float2bfloat16(x1);
                r2[e8 * 4 + 2] = __float2bfloat16(x2);
                r2[e8 * 4 + 3] = __float2bfloat16(x3);
                r1[e8 * 4 + 0] = __float2bfloat16(x0 + pv.x);
                r1[e8 * 4 + 1] = __float2bfloat16(x1 + pv.y);
                r1[e8 * 4 + 2] = __float2bfloat16(x2 + pv.z);
                r1[e8 * 4 + 3] = __float2bfloat16(x3 + pv.w);
            }
            uint4* d1 = (uint4*)(A1 + sl * ALD + wp * 32);
            uint4* d2 = (uint4*)(A2 + sl * ALD + wp * 32);
#pragma unroll
            for (int k = 0; k < 4; k++) {
                d1[k] = ((uint4*)r1)[k];
                d2[k] = ((uint4*)r2)[k];
            }
            __syncwarp();
        }
    }

    // per-lane deterministic column accumulators: slot = ch*2 + half
    float a1r[8], a2r[8];

    __nv_bfloat16* Wk_s = (__nv_bfloat16*)(sm + SWR);
    __nv_bfloat16* Wv_s = (__nv_bfloat16*)(sm + SWR + 33792);

    for (int ch = 0; ch < 4; ch++) {
        const int c0 = ch * 64;
        __syncthreads();   // staging/prev-chunk reads done before W overwrite
        // ---- load W chunks (64 c-rows x 256 e each), 528B padded rows ----
#pragma unroll
        for (int it = 0; it < 8; it++) {
            int idx = it * 256 + t;
            int row = idx >> 5, j = idx & 31;
            *(uint4*)((char*)Wk_s + row * 528 + j * 16) =
                *(const uint4*)(g_wTk + (size_t)(c0 + row) * E_DIM + j * 8);
            *(uint4*)((char*)Wv_s + row * 528 + j * 16) =
                *(const uint4*)(g_wTv + (size_t)(c0 + row) * E_DIM + j * 8);
        }
        __syncthreads();

        // ---- GEMM: warp wp owns rows 16wp..16wp+15, n = 64 (4 tiles) ----
        wmma::fragment<wmma::matrix_a, 16, 16, 16, __nv_bfloat16, wmma::row_major> a1f, a2f;
        wmma::fragment<wmma::matrix_b, 16, 16, 16, __nv_bfloat16, wmma::col_major> bf;
        wmma::fragment<wmma::accumulator, 16, 16, 16, float> acck[4], accv[4];
#pragma unroll
        for (int j = 0; j < 4; j++) {
            wmma::fill_fragment(acck[j], 0.0f);
            wmma::fill_fragment(accv[j], 0.0f);
        }
#pragma unroll
        for (int kk = 0; kk < 16; kk++) {
            int k = kk * 16;
            wmma::load_matrix_sync(a1f, A1 + (wp * 16) * ALD + k, ALD);
            wmma::load_matrix_sync(a2f, A2 + (wp * 16) * ALD + k, ALD);
#pragma unroll
            for (int j = 0; j < 4; j++) {
                wmma::load_matrix_sync(bf, Wk_s + (size_t)(j * 16) * ALD + k, ALD);
                wmma::mma_sync(acck[j], a1f, bf, acck[j]);
                wmma::load_matrix_sync(bf, Wv_s + (size_t)(j * 16) * ALD + k, ALD);
                wmma::mma_sync(accv[j], a2f, bf, accv[j]);
            }
        }
        __syncthreads();   // all warps done reading W before staging overwrite

        // ---- stage C into W region (per-warp private), exp + 16-row colsum ----
        float* st1 = (float*)(sm + SWR) + wp * 2176;
        float* st2 = st1 + 1088;
#pragma unroll
        for (int j = 0; j < 4; j++) {
            wmma::store_matrix_sync(st1 + j * 16, acck[j], 68, wmma::mem_row_major);
            wmma::store_matrix_sync(st2 + j * 16, accv[j], 68, wmma::mem_row_major);
        }
        __syncwarp();
#pragma unroll
        for (int half = 0; half < 2; half++) {
            int cl = half * 32 + lane;
            float a1 = 0.0f, a2 = 0.0f;
#pragma unroll
            for (int r = 0; r < 16; r++) {
                float e = __expf(st1[r * 68 + cl]);
                a1 += e;
                a2 += e * st2[r * 68 + cl];
            }
            a1r[ch * 2 + half] = a1;
            a2r[ch * 2 + half] = a2;
        }
    }
    __syncthreads();

    // ---- deterministic cross-warp reduce ----
    float* sw1 = (float*)(sm + SWR);           // [8][256]
    float* sw2 = sw1 + 2048;
#pragma unroll
    for (int ch = 0; ch < 4; ch++) {
#pragma unroll
        for (int half = 0; half < 2; half++) {
            int c = ch * 64 + half * 32 + lane;
            sw1[wp * 256 + c] = a1r[ch * 2 + half];
            sw2[wp * 256 + c] = a2r[ch * 2 + half];
        }
    }
    __syncthreads();
    {
        float s1 = 0.0f, s2 = 0.0f;
#pragma unroll
        for (int w = 0; w < 8; w++) {
            s1 += sw1[w * 256 + t];
            s2 += sw2[w * 256 + t];
        }
        g_Ps1[(size_t)t * NPARTS + bid] = s1;
        g_Ps2[(size_t)t * NPARTS + bid] = s2;
    }
}

// ---------------- kB: reduce partials -> context ----------------
__global__ void kB(const float* __restrict__ la_bv) {
    int c = blockIdx.x, t = threadIdx.x;
    float s1 = 0.0f, s2 = 0.0f;
#pragma unroll
    for (int j = 0; j < NPARTS / 256; j++) {
        s1 += g_Ps1[(size_t)c * NPARTS + j * 256 + t];
        s2 += g_Ps2[(size_t)c * NPARTS + j * 256 + t];
    }
    s1 = blkSum256(s1);
    s2 = blkSum256(s2);
    if (t == 0) g_ctx[c] = s2 / s1 + la_bv[c];   // la_bk cancels in softmax ratio
}

// ---------------- kC: all 3 refinement steps, one block per token (row-local) ----------------
// smem floats: KPs 6912 | VPs 6912 | qpr 256 | f 256 | X 256 | q 256 | y 256 |
//              part 1024 | scr 216 | al 216 | h1 2048   = 18608 floats = 74432 B
__global__ void __launch_bounds__(1024, 1) kC(
    const float* __restrict__ wq, const float* __restrict__ bq,
    const float* __restrict__ wo, const float* __restrict__ bo,
    const float* __restrict__ n1g, const float* __restrict__ n1b,
    const float* __restrict__ lawq, const float* __restrict__ labq,
    const float* __restrict__ n2g, const float* __restrict__ n2b,
    const float* __restrict__ w1, const float* __restrict__ b1,
    const float* __restrict__ w2, const float* __restrict__ b2,
    const float* __restrict__ n3g, const float* __restrict__ n3b,
    float* __restrict__ out) {
    extern __shared__ float s[];
    float* KPs = s;
    float* VPs = KPs + NTOK * 256;
    float* qpr = VPs + NTOK * 256;
    float* f   = qpr + 256;
    float* X   = f + 256;
    float* q   = X + 256;
    float* y   = q + 256;
    float* part= y + 256;
    float* scr = part + 1024;
    float* al  = scr + 8 * NTOK;
    float* h1  = al + 8 * NTOK;

    const int n = blockIdx.x, t = threadIdx.x;
    const int c = t & 255, p = t >> 8;

    for (int i = t; i < NTOK * 256; i += 1024) { KPs[i] = g_KP[i]; VPs[i] = g_VP[i]; }
    if (t < 256) { qpr[t] = g_QP[n * 256 + t]; f[t] = g_Fk[n * 256 + t]; }
    __syncthreads();

    for (int step = 0; step < 3; step++) {
        // ======== 1) MHA cross-attention + LN1 ========
        if (t < 256) X[t] = f[t] + qpr[t];
        __syncthreads();
        {   // q projection (4-way K split)
            float a = (p == 0) ? bq[c] : 0.0f;
            const float* w = wq + (size_t)(p * 64) * 256 + c;
            const float* xx = X + p * 64;
#pragma unroll 8
            for (int e = 0; e < 64; e++) a += xx[e] * w[e * 256];
            part[t] = a;
        }
        __syncthreads();
        if (t < 256) q[t] = part[t] + part[256 + t] + part[512 + t] + part[768 + t];
        __syncthreads();
        if (t < 8 * NTOK) {
            int h = t / NTOK, sx = t % NTOK;
            float a = 0.0f;
#pragma unroll
            for (int d = 0; d < 32; d++) a += q[h * 32 + d] * KPs[sx * 256 + h * 32 + d];
            scr[t] = a * 0.17677669529663689f;
        }
        __syncthreads();
        if (t < 8) {
            float m = -1e30f;
            for (int sx = 0; sx < NTOK; sx++) m = fmaxf(m, scr[t * NTOK + sx]);
            float su = 0.0f;
            for (int sx = 0; sx < NTOK; sx++) {
                float e = __expf(scr[t * NTOK + sx] - m);
                al[t * NTOK + sx] = e;
                su += e;
            }
            float inv = 1.0f / su;
            for (int sx = 0; sx < NTOK; sx++) al[t * NTOK + sx] *= inv;
        }
        __syncthreads();
        if (t < 256) {
            int h = t >> 5;
            float a = 0.0f;
#pragma unroll
            for (int sx = 0; sx < NTOK; sx++) a += al[h * NTOK + sx] * VPs[sx * 256 + t];
            X[t] = a;   // X = attention output
        }
        __syncthreads();
        {   // o projection
            float a = (p == 0) ? bo[c] : 0.0f;
            const float* w = wo + (size_t)(p * 64) * 256 + c;
            const float* xx = X + p * 64;
#pragma unroll 8
            for (int e = 0; e < 64; e++) a += xx[e] * w[e * 256];
            part[t] = a;
        }
        __syncthreads();
        if (t < 256) y[t] = f[t] + part[t] + part[256 + t] + part[512 + t] + part[768 + t];
        __syncthreads();
        {   // LN1
            float v = (t < 256) ? y[t] : 0.0f;
            float m = bSum(v) * (1.0f / 256.0f);
            float d = (t < 256) ? (y[t] - m) : 0.0f;
            float var = bSum(d * d) * (1.0f / 256.0f);
            if (t < 256) f[t] = d * rsqrtf(var + 1e-5f) * n1g[t] + n1b[t];
        }
        __syncthreads();

        // ======== 2) Linear attention + LN2 ========
        if (t < 256) X[t] = f[t] + qpr[t];
        __syncthreads();
        {
            float a = (p == 0) ? labq[c] : 0.0f;
            const float* w = lawq + (size_t)(p * 64) * 256 + c;
            const float* xx = X + p * 64;
#pragma unroll 8
            for (int e = 0; e < 64; e++) a += xx[e] * w[e * 256];
            part[t] = a;
        }
        __syncthreads();
        {
            float qa = 0.0f;
            if (t < 256) qa = (part[t] + part[256 + t] + part[512 + t] + part[768 + t]) * 0.0625f;
            float mv = bMax((t < 256) ? qa : -1e30f);
            float ev = (t < 256) ? __expf(qa - mv) : 0.0f;
            float sv = bSum(ev);
            if (t < 256) y[t] = f[t] + (ev / sv) * g_ctx[t];
        }
        __syncthreads();
        {   // LN2
            float v = (t < 256) ? y[t] : 0.0f;
            float m = bSum(v) * (1.0f / 256.0f);
            float d = (t < 256) ? (y[t] - m) : 0.0f;
            float var = bSum(d * d) * (1.0f / 256.0f);
            if (t < 256) f[t] = d * rsqrtf(var + 1e-5f) * n2g[t] + n2b[t];
        }
        __syncthreads();

        // ======== 3) FFN + LN3 ========
        {
#pragma unroll
            for (int o = 0; o < 2; o++) {
                int cc = t + o * 1024;
                float a = b1[cc];
                const float* w = w1 + cc;
#pragma unroll 8
                for (int e = 0; e < 256; e++) a += f[e] * w[(size_t)e * FFD];
                h1[cc] = gelu_exact(a);
            }
        }
        __syncthreads();
        {
            float a = (p == 0) ? b2[c] : 0.0f;
            const float* w = w2 + (size_t)(p * 512) * 256 + c;
            const float* hh = h1 + p * 512;
#pragma unroll 8
            for (int j = 0; j < 512; j++) a += hh[j] * w[(size_t)j * 256];
            part[t] = a;
        }
        __syncthreads();
        if (t < 256) y[t] = f[t] + part[t] + part[256 + t] + part[512 + t] + part[768 + t];
        __syncthreads();
        {   // LN3 + output broadcast over batch
            float v = (t < 256) ? y[t] : 0.0f;
            float m = bSum(v) * (1.0f / 256.0f);
            float d = (t < 256) ? (y[t] - m) : 0.0f;
            float var = bSum(d * d) * (1.0f / 256.0f);
            if (t < 256) {
                float r = d * rsqrtf(var + 1e-5f) * n3g[t] + n3b[t];
                f[t] = r;
                float* o = out + ((size_t)(step * NTOK + n) * BS) * 256 + t;
#pragma unroll
                for (int b = 0; b < BS; b++) o[b * 256] = r;
            }
        }
        __syncthreads();
    }
}

// ---------------- launch ----------------
extern "C" void kernel_launch(void* const* d_in, const int* in_sizes, int n_in,
                              void* d_out, int out_size) {
    const float* f_e      = (const float*)d_in[0];
    const float* pos_emb  = (const float*)d_in[1];
    const float* shape_map= (const float*)d_in[3];
    const float* mha_wq   = (const float*)d_in[4];
    const float* mha_bq   = (const float*)d_in[5];
    const float* mha_wk   = (const float*)d_in[6];
    const float* mha_bk   = (const float*)d_in[7];
    const float* mha_wv   = (const float*)d_in[8];
    const float* mha_bv   = (const float*)d_in[9];
    const float* mha_wo   = (const float*)d_in[10];
    const float* mha_bo   = (const float*)d_in[11];
    const float* la_wq    = (const float*)d_in[12];
    const float* la_bq    = (const float*)d_in[13];
    const float* la_wk    = (const float*)d_in[14];
    const float* la_wv    = (const float*)d_in[16];
    const float* la_bv    = (const float*)d_in[17];
    const float* ff_w1    = (const float*)d_in[18];
    const float* ff_b1    = (const float*)d_in[19];
    const float* ff_w2    = (const float*)d_in[20];
    const float* ff_b2    = (const float*)d_in[21];
    const float* n1_g     = (const float*)d_in[22];
    const float* n1_b     = (const float*)d_in[23];
    const float* n2_g     = (const float*)d_in[24];
    const float* n2_b     = (const float*)d_in[25];
    const float* n3_g     = (const float*)d_in[26];
    const float* n3_b     = (const float*)d_in[27];
    float* out = (float*)d_out;

    cudaFuncSetAttribute(kA, cudaFuncAttributeMaxDynamicSharedMemorySize, SMEM_KA);
    cudaFuncSetAttribute(kC, cudaFuncAttributeMaxDynamicSharedMemorySize, 80 * 1024);
    const int kc_smem = (2 * NTOK * 256 + 5 * 256 + 1024 + 2 * 8 * NTOK + 2048) * 4;

    kPrep<<<NTOK + 1 + 256, 256>>>(shape_map, mha_wk, mha_bk, mha_wv, mha_bv, la_wk, la_wv);
    kA<<<dim3(32, BS), 256, SMEM_KA>>>(f_e, pos_emb);
    kB<<<E_DIM, 256>>>(la_bv);
    kC<<<NTOK, 1024, kc_smem>>>(mha_wq, mha_bq, mha_wo, mha_bo, n1_g, n1_b,
                                la_wq, la_bq, n2_g, n2_b,
                                ff_w1, ff_b1, ff_w2, ff_b2, n3_g, n3_b, out);
}

// round 5
// speedup vs baseline: 3.1278x; 1.0587x over previous
#include <cuda_runtime.h>
#include <cuda_bf16.h>
#include <mma.h>
#include <cstdint>

using namespace nvcuda;

#define E_DIM 256
#define HW    4096
#define BS    32
#define NTOK  27
#define FFD   2048
#define NPARTS 1024

// ---------------- device scratch ----------------
__device__ __nv_bfloat16 g_wTk[E_DIM * E_DIM];   // Wk^T [c][e] bf16
__device__ __nv_bfloat16 g_wTv[E_DIM * E_DIM];   // Wv^T [c][e] bf16
__device__ float g_Ps1[E_DIM * NPARTS];          // [c][part]
__device__ float g_Ps2[E_DIM * NPARTS];
__device__ float g_ctx[E_DIM];
__device__ float g_QP[NTOK * E_DIM];
__device__ float g_KP[NTOK * E_DIM];
__device__ float g_VP[NTOK * E_DIM];
__device__ float g_Fk[NTOK * E_DIM];

// ---------------- helpers ----------------
__device__ __forceinline__ float blkSum256(float v) {
    __shared__ float sh[8];
    int lane = threadIdx.x & 31, w = threadIdx.x >> 5;
#pragma unroll
    for (int o = 16; o > 0; o >>= 1) v += __shfl_xor_sync(0xffffffffu, v, o);
    __syncthreads();
    if (lane == 0) sh[w] = v;
    __syncthreads();
    float r = sh[lane & 7];
#pragma unroll
    for (int o = 4; o > 0; o >>= 1) r += __shfl_xor_sync(0xffffffffu, r, o);
    return r;
}

// 1024-thread block reductions (kC)
__device__ __forceinline__ float bSum(float v) {
    __shared__ float sh[33];
    int lane = threadIdx.x & 31, w = threadIdx.x >> 5;
#pragma unroll
    for (int o = 16; o > 0; o >>= 1) v += __shfl_xor_sync(0xffffffffu, v, o);
    if (lane == 0) sh[w] = v;
    __syncthreads();
    if (w == 0) {
        float r = sh[lane];
#pragma unroll
        for (int o = 16; o > 0; o >>= 1) r += __shfl_xor_sync(0xffffffffu, r, o);
        if (lane == 0) sh[32] = r;
    }
    __syncthreads();
    float r = sh[32];
    __syncthreads();
    return r;
}
__device__ __forceinline__ float bMax(float v) {
    __shared__ float sh2[33];
    int lane = threadIdx.x & 31, w = threadIdx.x >> 5;
#pragma unroll
    for (int o = 16; o > 0; o >>= 1) v = fmaxf(v, __shfl_xor_sync(0xffffffffu, v, o));
    if (lane == 0) sh2[w] = v;
    __syncthreads();
    if (w == 0) {
        float r = sh2[lane];
#pragma unroll
        for (int o = 16; o > 0; o >>= 1) r = fmaxf(r, __shfl_xor_sync(0xffffffffu, r, o));
        if (lane == 0) sh2[32] = r;
    }
    __syncthreads();
    float r = sh2[32];
    __syncthreads();
    return r;
}
__device__ __forceinline__ float gelu_exact(float v) {
    return 0.5f * v * (1.0f + erff(v * 0.7071067811865475f));
}

// 256x256 matvec, float4 cols + 16-way depth split. 1024 threads.
// part: [16][256] floats. Caller syncs and reduces.
__device__ __forceinline__ void proj256(const float* __restrict__ w,
                                        const float* __restrict__ xin,
                                        float* __restrict__ part, int t) {
    int g = t & 63, dseg = t >> 6;
    const float4* w4 = (const float4*)w;
    const float* xx = xin + dseg * 16;
    float4 acc = make_float4(0.f, 0.f, 0.f, 0.f);
    int base = dseg * 16 * 64 + g;
#pragma unroll
    for (int e = 0; e < 16; e++) {
        float4 wv = w4[base + e * 64];
        float xv = xx[e];
        acc.x += xv * wv.x; acc.y += xv * wv.y;
        acc.z += xv * wv.z; acc.w += xv * wv.w;
    }
    ((float4*)part)[dseg * 64 + g] = acc;
}

// ---------------- kPrep ----------------
__global__ void kPrep(const float* __restrict__ shape_map,
                      const float* __restrict__ mha_wk, const float* __restrict__ mha_bk,
                      const float* __restrict__ mha_wv, const float* __restrict__ mha_bv,
                      const float* __restrict__ la_wk, const float* __restrict__ la_wv) {
    int blk = blockIdx.x, t = threadIdx.x;
    if (blk < NTOK) {
        __shared__ float x[E_DIM];
        float f = shape_map[blk * E_DIM + t];
        x[t] = f;
        g_Fk[blk * E_DIM + t] = f;
        __syncthreads();
        float ak = mha_bk[t], av = mha_bv[t];
#pragma unroll 4
        for (int e = 0; e < E_DIM; e++) {
            float xe = x[e];
            ak += xe * mha_wk[e * E_DIM + t];
            av += xe * mha_wv[e * E_DIM + t];
        }
        g_KP[blk * E_DIM + t] = ak;
        g_VP[blk * E_DIM + t] = av;
    } else if (blk == NTOK) {
        for (int n = 0; n < NTOK; n++) {
            int j = n % 9;
            float pos = (t < 128) ? (float)(j / 3 + 1) : (float)(j % 3 + 1);
            int k = (t & 127) >> 1;
            float arg = pos / powf(10000.0f, (float)k / 64.0f);
            g_QP[n * E_DIM + t] = (t & 1) ? cosf(arg) : sinf(arg);
        }
    } else {
        int i = (blk - NTOK - 1) * 256 + t;   // i = e*256 + c
        int e = i >> 8, c = i & 255;
        g_wTk[c * E_DIM + e] = __float2bfloat16(la_wk[i]);
        g_wTv[c * E_DIM + e] = __float2bfloat16(la_wv[i]);
    }
}

// ---------------- kA: Phase A, 512 threads, K/V warp-specialized WMMA ----------------
#define ALD 264             // bf16 elems per row (528 B)
#define SA1 0
#define SA2 67584
#define SWR 135168          // 69632 B multi-purpose region
#define SMEM_KA 204800

__global__ void __launch_bounds__(512, 1) kA(const float* __restrict__ f_e,
                                             const float* __restrict__ pos) {
    extern __shared__ char sm[];
    __nv_bfloat16* A1 = (__nv_bfloat16*)(sm + SA1);
    __nv_bfloat16* A2 = (__nv_bfloat16*)(sm + SA2);
    __shared__ float psum1[8][64];
    __shared__ float psum2[8][64];

    const int t = threadIdx.x, lane = t & 31, wp = t >> 5;
    const int sblk = blockIdx.x, b = blockIdx.y;
    const int bid = b * 32 + sblk;

    // ---- fused transpose load: f_e [b][e][s] -> A2 [s][e]; A1 = A2 + pos ----
    {
        float* tl = (float*)(sm + SWR) + wp * (32 * 33);   // 16 warps * 4224B = 67584 <= 69632
        const int e0 = (wp & 7) * 32;
        const int h = wp >> 3;
        const float* src = f_e + ((size_t)b * E_DIM + e0) * HW + (size_t)sblk * 128 + h * 64;
#pragma unroll
        for (int ssub = 0; ssub < 2; ssub++) {
            const float* s2 = src + ssub * 32;
#pragma unroll
            for (int i = 0; i < 32; i++) tl[i * 33 + lane] = s2[(size_t)i * HW + lane];
            __syncwarp();
            int sl = h * 64 + ssub * 32 + lane;
            const float* prow = pos + ((size_t)(sblk * 128 + sl) * BS + b) * E_DIM + e0;
            __nv_bfloat16 r1[32], r2[32];
#pragma unroll
            for (int e8 = 0; e8 < 8; e8++) {
                float4 pv = *(const float4*)(prow + e8 * 4);
                float x0 = tl[(e8 * 4 + 0) * 33 + lane];
                float x1 = tl[(e8 * 4 + 1) * 33 + lane];
                float x2 = tl[(e8 * 4 + 2) * 33 + lane];
                float x3 = tl[(e8 * 4 + 3) * 33 + lane];
                r2[e8 * 4 + 0] = __float2bfloat16(x0);
                r2[e8 * 4 + 1] = __float2bfloat16(x1);
                r2[e8 * 4 + 2] = __float2bfloat16(x2);
                r2[e8 * 4 + 3] = __float2bfloat16(x3);
                r1[e8 * 4 + 0] = __float2bfloat16(x0 + pv.x);
                r1[e8 * 4 + 1] = __float2bfloat16(x1 + pv.y);
                r1[e8 * 4 + 2] = __float2bfloat16(x2 + pv.z);
                r1[e8 * 4 + 3] = __float2bfloat16(x3 + pv.w);
            }
            uint4* d1 = (uint4*)(A1 + sl * ALD + e0);
            uint4* d2 = (uint4*)(A2 + sl * ALD + e0);
#pragma unroll
            for (int k = 0; k < 4; k++) {
                d1[k] = ((uint4*)r1)[k];
                d2[k] = ((uint4*)r2)[k];
            }
            __syncwarp();
        }
    }

    __nv_bfloat16* Wk_s = (__nv_bfloat16*)(sm + SWR);            // 64 rows * 528B
    __nv_bfloat16* Wv_s = (__nv_bfloat16*)(sm + SWR + 33792);
    float* st1 = (float*)(sm + SWR);                              // 128 x 68 fp32
    float* st2 = (float*)(sm + SWR + 34816);

    const bool isK = (wp < 8);
    const int m0 = (wp & 7) * 16;
    const __nv_bfloat16* Aw = isK ? A1 : A2;

    for (int ch = 0; ch < 4; ch++) {
        const int c0 = ch * 64;
        __syncthreads();   // prior-phase reads of SWR done
        // ---- load W chunks: 64 c-rows x 256 e each (uint4 = 8 bf16) ----
#pragma unroll
        for (int it = 0; it < 4; it++) {
            int idx = it * 512 + t;
            int row = idx >> 5, j = idx & 31;
            *(uint4*)((char*)Wk_s + row * 528 + j * 16) =
                *(const uint4*)(g_wTk + (size_t)(c0 + row) * E_DIM + j * 8);
            *(uint4*)((char*)Wv_s + row * 528 + j * 16) =
                *(const uint4*)(g_wTv + (size_t)(c0 + row) * E_DIM + j * 8);
        }
        __syncthreads();

        // ---- GEMM: warp owns 16 m-rows x 64 n-cols, one matrix ----
        wmma::fragment<wmma::matrix_a, 16, 16, 16, __nv_bfloat16, wmma::row_major> af;
        wmma::fragment<wmma::matrix_b, 16, 16, 16, __nv_bfloat16, wmma::col_major> bf;
        wmma::fragment<wmma::accumulator, 16, 16, 16, float> acc[4];
#pragma unroll
        for (int j = 0; j < 4; j++) wmma::fill_fragment(acc[j], 0.0f);
        const __nv_bfloat16* Ws = isK ? Wk_s : Wv_s;
#pragma unroll
        for (int kk = 0; kk < 16; kk++) {
            int k = kk * 16;
            wmma::load_matrix_sync(af, Aw + (size_t)m0 * ALD + k, ALD);
#pragma unroll
            for (int j = 0; j < 4; j++) {
                wmma::load_matrix_sync(bf, Ws + (size_t)(j * 16) * ALD + k, ALD);
                wmma::mma_sync(acc[j], af, bf, acc[j]);
            }
        }
        __syncthreads();   // all W reads done before SWR reuse as staging

        // ---- stage: K-warps -> st1, V-warps -> st2 ----
        float* st = isK ? st1 : st2;
#pragma unroll
        for (int j = 0; j < 4; j++)
            wmma::store_matrix_sync(st + (size_t)m0 * 68 + j * 16, acc[j], 68, wmma::mem_row_major);
        __syncthreads();

        // ---- exp + columnwise product-sum over 128 rows ----
        {
            int c = t & 63, rseg = t >> 6;
            float a1 = 0.0f, a2 = 0.0f;
#pragma unroll
            for (int r = rseg * 16; r < rseg * 16 + 16; r++) {
                float e = __expf(st1[r * 68 + c]);
                a1 += e;
                a2 += e * st2[r * 68 + c];
            }
            psum1[rseg][c] = a1;
            psum2[rseg][c] = a2;
        }
        __syncthreads();
        if (t < 64) {
            float s1 = 0.0f;
#pragma unroll
            for (int k = 0; k < 8; k++) s1 += psum1[k][t];
            g_Ps1[(size_t)(c0 + t) * NPARTS + bid] = s1;
        } else if (t < 128) {
            int c = t - 64;
            float s2 = 0.0f;
#pragma unroll
            for (int k = 0; k < 8; k++) s2 += psum2[k][c];
            g_Ps2[(size_t)(c0 + c) * NPARTS + bid] = s2;
        }
    }
}

// ---------------- kB: reduce partials -> context ----------------
__global__ void kB(const float* __restrict__ la_bv) {
    int c = blockIdx.x, t = threadIdx.x;
    float s1 = 0.0f, s2 = 0.0f;
#pragma unroll
    for (int j = 0; j < NPARTS / 256; j++) {
        s1 += g_Ps1[(size_t)c * NPARTS + j * 256 + t];
        s2 += g_Ps2[(size_t)c * NPARTS + j * 256 + t];
    }
    s1 = blkSum256(s1);
    s2 = blkSum256(s2);
    if (t == 0) g_ctx[c] = s2 / s1 + la_bv[c];   // la_bk cancels in softmax ratio
}

// ---------------- kC: all 3 refinement steps, one block per token ----------------
// smem floats: KPs 6912 | VPs 6912 | h1 2048 | part 4096 | qpr/f/X/q/y 256*5 | scr 216 | al 216
__global__ void __launch_bounds__(1024, 1) kC(
    const float* __restrict__ wq, const float* __restrict__ bq,
    const float* __restrict__ wo, const float* __restrict__ bo,
    const float* __restrict__ n1g, const float* __restrict__ n1b,
    const float* __restrict__ lawq, const float* __restrict__ labq,
    const float* __restrict__ n2g, const float* __restrict__ n2b,
    const float* __restrict__ w1, const float* __restrict__ b1,
    const float* __restrict__ w2, const float* __restrict__ b2,
    const float* __restrict__ n3g, const float* __restrict__ n3b,
    float* __restrict__ out) {
    extern __shared__ float s[];
    float* KPs = s;
    float* VPs = KPs + NTOK * 256;
    float* h1  = VPs + NTOK * 256;
    float* part= h1 + FFD;
    float* qpr = part + 4096;
    float* f   = qpr + 256;
    float* X   = f + 256;
    float* q   = X + 256;
    float* y   = q + 256;
    float* scr = y + 256;
    float* al  = scr + 8 * NTOK;

    const int n = blockIdx.x, t = threadIdx.x;

    for (int i = t; i < NTOK * 256; i += 1024) { KPs[i] = g_KP[i]; VPs[i] = g_VP[i]; }
    if (t < 256) { qpr[t] = g_QP[n * 256 + t]; f[t] = g_Fk[n * 256 + t]; }
    __syncthreads();

    for (int step = 0; step < 3; step++) {
        // ======== 1) MHA cross-attention + LN1 ========
        if (t < 256) X[t] = f[t] + qpr[t];
        __syncthreads();
        proj256(wq, X, part, t);
        __syncthreads();
        if (t < 256) {
            float a = bq[t];
#pragma unroll
            for (int k = 0; k < 16; k++) a += part[k * 256 + t];
            q[t] = a;
        }
        __syncthreads();
        if (t < 8 * NTOK) {
            int h = t / NTOK, sx = t % NTOK;
            float a = 0.0f;
#pragma unroll
            for (int d = 0; d < 32; d++) a += q[h * 32 + d] * KPs[sx * 256 + h * 32 + d];
            scr[t] = a * 0.17677669529663689f;
        }
        __syncthreads();
        if (t < 8) {
            float m = -1e30f;
            for (int sx = 0; sx < NTOK; sx++) m = fmaxf(m, scr[t * NTOK + sx]);
            float su = 0.0f;
            for (int sx = 0; sx < NTOK; sx++) {
                float e = __expf(scr[t * NTOK + sx] - m);
                al[t * NTOK + sx] = e;
                su += e;
            }
            float inv = 1.0f / su;
            for (int sx = 0; sx < NTOK; sx++) al[t * NTOK + sx] *= inv;
        }
        __syncthreads();
        if (t < 256) {
            int h = t >> 5;
            float a = 0.0f;
#pragma unroll
            for (int sx = 0; sx < NTOK; sx++) a += al[h * NTOK + sx] * VPs[sx * 256 + t];
            X[t] = a;
        }
        __syncthreads();
        proj256(wo, X, part, t);
        __syncthreads();
        if (t < 256) {
            float a = bo[t];
#pragma unroll
            for (int k = 0; k < 16; k++) a += part[k * 256 + t];
            y[t] = f[t] + a;
        }
        __syncthreads();
        {   // LN1
            float v = (t < 256) ? y[t] : 0.0f;
            float m = bSum(v) * (1.0f / 256.0f);
            float d = (t < 256) ? (y[t] - m) : 0.0f;
            float var = bSum(d * d) * (1.0f / 256.0f);
            if (t < 256) f[t] = d * rsqrtf(var + 1e-5f) * n1g[t] + n1b[t];
        }
        __syncthreads();

        // ======== 2) Linear attention + LN2 ========
        if (t < 256) X[t] = f[t] + qpr[t];
        __syncthreads();
        proj256(lawq, X, part, t);
        __syncthreads();
        {
            float qa = 0.0f;
            if (t < 256) {
                qa = labq[t];
#pragma unroll
                for (int k = 0; k < 16; k++) qa += part[k * 256 + t];
                qa *= 0.0625f;
            }
            float mv = bMax((t < 256) ? qa : -1e30f);
            float ev = (t < 256) ? __expf(qa - mv) : 0.0f;
            float sv = bSum(ev);
            if (t < 256) y[t] = f[t] + (ev / sv) * g_ctx[t];
        }
        __syncthreads();
        {   // LN2
            float v = (t < 256) ? y[t] : 0.0f;
            float m = bSum(v) * (1.0f / 256.0f);
            float d = (t < 256) ? (y[t] - m) : 0.0f;
            float var = bSum(d * d) * (1.0f / 256.0f);
            if (t < 256) f[t] = d * rsqrtf(var + 1e-5f) * n2g[t] + n2b[t];
        }
        __syncthreads();

        // ======== 3) FFN + LN3 ========
        {   // h1 = gelu(f @ w1 + b1): 512 col-groups x 2 depth-segs
            int g = t & 511, dseg = t >> 9;
            const float4* w4 = (const float4*)w1;
            const float* xx = f + dseg * 128;
            float4 acc = make_float4(0.f, 0.f, 0.f, 0.f);
            int base = dseg * 128 * 512 + g;
#pragma unroll 4
            for (int e = 0; e < 128; e++) {
                float4 wv = w4[base + e * 512];
                float xv = xx[e];
                acc.x += xv * wv.x; acc.y += xv * wv.y;
                acc.z += xv * wv.z; acc.w += xv * wv.w;
            }
            ((float4*)part)[dseg * 512 + g] = acc;
        }
        __syncthreads();
#pragma unroll
        for (int o = 0; o < 2; o++) {
            int cc = t + o * 1024;
            h1[cc] = gelu_exact(b1[cc] + part[cc] + part[2048 + cc]);
        }
        __syncthreads();
        {   // y = f + h1 @ w2 + b2: 64 col-groups x 16 depth-segs
            int g = t & 63, dseg = t >> 6;
            const float4* w4 = (const float4*)w2;
            const float* hh = h1 + dseg * 128;
            float4 acc = make_float4(0.f, 0.f, 0.f, 0.f);
            int base = dseg * 128 * 64 + g;
#pragma unroll 4
            for (int j = 0; j < 128; j++) {
                float4 wv = w4[base + j * 64];
                float hv = hh[j];
                acc.x += hv * wv.x; acc.y += hv * wv.y;
                acc.z += hv * wv.z; acc.w += hv * wv.w;
            }
            ((float4*)part)[dseg * 64 + g] = acc;
        }
        __syncthreads();
        if (t < 256) {
            float a = b2[t];
#pragma unroll
            for (int k = 0; k < 16; k++) a += part[k * 256 + t];
            y[t] = f[t] + a;
        }
        __syncthreads();
        {   // LN3 + batch-broadcast output
            float v = (t < 256) ? y[t] : 0.0f;
            float m = bSum(v) * (1.0f / 256.0f);
            float d = (t < 256) ? (y[t] - m) : 0.0f;
            float var = bSum(d * d) * (1.0f / 256.0f);
            if (t < 256) {
                float r = d * rsqrtf(var + 1e-5f) * n3g[t] + n3b[t];
                f[t] = r;
                float* o = out + ((size_t)(step * NTOK + n) * BS) * 256 + t;
#pragma unroll
                for (int b = 0; b < BS; b++) o[b * 256] = r;
            }
        }
        __syncthreads();
    }
}

// ---------------- launch ----------------
extern "C" void kernel_launch(void* const* d_in, const int* in_sizes, int n_in,
                              void* d_out, int out_size) {
    const float* f_e      = (const float*)d_in[0];
    const float* pos_emb  = (const float*)d_in[1];
    const float* shape_map= (const float*)d_in[3];
    const float* mha_wq   = (const float*)d_in[4];
    const float* mha_bq   = (const float*)d_in[5];
    const float* mha_wk   = (const float*)d_in[6];
    const float* mha_bk   = (const float*)d_in[7];
    const float* mha_wv   = (const float*)d_in[8];
    const float* mha_bv   = (const float*)d_in[9];
    const float* mha_wo   = (const float*)d_in[10];
    const float* mha_bo   = (const float*)d_in[11];
    const float* la_wq    = (const float*)d_in[12];
    const float* la_bq    = (const float*)d_in[13];
    const float* la_wk    = (const float*)d_in[14];
    const float* la_wv    = (const float*)d_in[16];
    const float* la_bv    = (const float*)d_in[17];
    const float* ff_w1    = (const float*)d_in[18];
    const float* ff_b1    = (const float*)d_in[19];
    const float* ff_w2    = (const float*)d_in[20];
    const float* ff_b2    = (const float*)d_in[21];
    const float* n1_g     = (const float*)d_in[22];
    const float* n1_b     = (const float*)d_in[23];
    const float* n2_g     = (const float*)d_in[24];
    const float* n2_b     = (const float*)d_in[25];
    const float* n3_g     = (const float*)d_in[26];
    const float* n3_b     = (const float*)d_in[27];
    float* out = (float*)d_out;

    cudaFuncSetAttribute(kA, cudaFuncAttributeMaxDynamicSharedMemorySize, SMEM_KA);
    cudaFuncSetAttribute(kC, cudaFuncAttributeMaxDynamicSharedMemorySize, 100 * 1024);
    const int kc_smem = (2 * NTOK * 256 + FFD + 4096 + 5 * 256 + 2 * 8 * NTOK) * 4;

    kPrep<<<NTOK + 1 + 256, 256>>>(shape_map, mha_wk, mha_bk, mha_wv, mha_bv, la_wk, la_wv);
    kA<<<dim3(32, BS), 512, SMEM_KA>>>(f_e, pos_emb);
    kB<<<E_DIM, 256>>>(la_bv);
    kC<<<NTOK, 1024, kc_smem>>>(mha_wq, mha_bq, mha_wo, mha_bo, n1_g, n1_b,
                                la_wq, la_bq, n2_g, n2_b,
                                ff_w1, ff_b1, ff_w2, ff_b2, n3_g, n3_b, out);
}

// round 6
// speedup vs baseline: 3.4462x; 1.1018x over previous
#include <cuda_runtime.h>
#include <cuda_bf16.h>
#include <mma.h>
#include <cstdint>

using namespace nvcuda;

#define E_DIM 256
#define HW    4096
#define BS    32
#define NTOK  27
#define FFD   2048
#define NPARTS 1024

// ---------------- device scratch ----------------
__device__ __nv_bfloat16 g_wTk[E_DIM * E_DIM];   // Wk^T [c][e] bf16 (phase A)
__device__ __nv_bfloat16 g_wTv[E_DIM * E_DIM];   // Wv^T [c][e] bf16
__device__ __nv_bfloat16 g_bq[E_DIM * E_DIM];    // mha_wq bf16 [e][c]
__device__ __nv_bfloat16 g_bo[E_DIM * E_DIM];    // mha_wo bf16
__device__ __nv_bfloat16 g_bl[E_DIM * E_DIM];    // la_wq  bf16
__device__ __nv_bfloat16 g_b1[E_DIM * FFD];      // ff_w1  bf16
__device__ __nv_bfloat16 g_b2[FFD * E_DIM];      // ff_w2  bf16
__device__ float g_Ps1[E_DIM * NPARTS];
__device__ float g_Ps2[E_DIM * NPARTS];
__device__ float g_ctx[E_DIM];
__device__ float g_QP[NTOK * E_DIM];
__device__ float g_KP[NTOK * E_DIM];
__device__ float g_VP[NTOK * E_DIM];
__device__ float g_Fk[NTOK * E_DIM];

// ---------------- helpers ----------------
__device__ __forceinline__ float blkSum256(float v) {
    __shared__ float sh[8];
    int lane = threadIdx.x & 31, w = threadIdx.x >> 5;
#pragma unroll
    for (int o = 16; o > 0; o >>= 1) v += __shfl_xor_sync(0xffffffffu, v, o);
    __syncthreads();
    if (lane == 0) sh[w] = v;
    __syncthreads();
    float r = sh[lane & 7];
#pragma unroll
    for (int o = 4; o > 0; o >>= 1) r += __shfl_xor_sync(0xffffffffu, r, o);
    return r;
}
__device__ __forceinline__ float bSum(float v) {
    __shared__ float sh[33];
    int lane = threadIdx.x & 31, w = threadIdx.x >> 5;
#pragma unroll
    for (int o = 16; o > 0; o >>= 1) v += __shfl_xor_sync(0xffffffffu, v, o);
    if (lane == 0) sh[w] = v;
    __syncthreads();
    if (w == 0) {
        float r = sh[lane];
#pragma unroll
        for (int o = 16; o > 0; o >>= 1) r += __shfl_xor_sync(0xffffffffu, r, o);
        if (lane == 0) sh[32] = r;
    }
    __syncthreads();
    float r = sh[32];
    __syncthreads();
    return r;
}
__device__ __forceinline__ float bMax(float v) {
    __shared__ float sh2[33];
    int lane = threadIdx.x & 31, w = threadIdx.x >> 5;
#pragma unroll
    for (int o = 16; o > 0; o >>= 1) v = fmaxf(v, __shfl_xor_sync(0xffffffffu, v, o));
    if (lane == 0) sh2[w] = v;
    __syncthreads();
    if (w == 0) {
        float r = sh2[lane];
#pragma unroll
        for (int o = 16; o > 0; o >>= 1) r = fmaxf(r, __shfl_xor_sync(0xffffffffu, r, o));
        if (lane == 0) sh2[32] = r;
    }
    __syncthreads();
    float r = sh2[32];
    __syncthreads();
    return r;
}
__device__ __forceinline__ float gelu_exact(float v) {
    return 0.5f * v * (1.0f + erff(v * 0.7071067811865475f));
}
__device__ __forceinline__ void bf8_fma(uint4 wv, float xv, float* acc) {
    const __nv_bfloat162* p = (const __nv_bfloat162*)&wv;
#pragma unroll
    for (int k = 0; k < 4; k++) {
        float2 f2 = __bfloat1622float2(p[k]);
        acc[2 * k]     += xv * f2.x;
        acc[2 * k + 1] += xv * f2.y;
    }
}

// ---------------- kConv: fp32 -> bf16 weight conversion for kC ----------------
__global__ void kConv(const float* __restrict__ wq, const float* __restrict__ wo,
                      const float* __restrict__ lq, const float* __restrict__ w1,
                      const float* __restrict__ w2) {
    int i = blockIdx.x * 256 + threadIdx.x;
    if (i < 65536)        g_bq[i] = __float2bfloat16(wq[i]);
    else if (i < 131072)  g_bo[i - 65536] = __float2bfloat16(wo[i - 65536]);
    else if (i < 196608)  g_bl[i - 131072] = __float2bfloat16(lq[i - 131072]);
    else if (i < 720896)  g_b1[i - 196608] = __float2bfloat16(w1[i - 196608]);
    else if (i < 1245184) g_b2[i - 720896] = __float2bfloat16(w2[i - 720896]);
}

// ---------------- kPrep ----------------
__global__ void kPrep(const float* __restrict__ shape_map,
                      const float* __restrict__ mha_wk, const float* __restrict__ mha_bk,
                      const float* __restrict__ mha_wv, const float* __restrict__ mha_bv,
                      const float* __restrict__ la_wk, const float* __restrict__ la_wv) {
    int blk = blockIdx.x, t = threadIdx.x;
    if (blk < NTOK) {
        __shared__ float x[E_DIM];
        float f = shape_map[blk * E_DIM + t];
        x[t] = f;
        g_Fk[blk * E_DIM + t] = f;
        __syncthreads();
        float ak = mha_bk[t], av = mha_bv[t];
#pragma unroll 4
        for (int e = 0; e < E_DIM; e++) {
            float xe = x[e];
            ak += xe * mha_wk[e * E_DIM + t];
            av += xe * mha_wv[e * E_DIM + t];
        }
        g_KP[blk * E_DIM + t] = ak;
        g_VP[blk * E_DIM + t] = av;
    } else if (blk == NTOK) {
        for (int n = 0; n < NTOK; n++) {
            int j = n % 9;
            float pos = (t < 128) ? (float)(j / 3 + 1) : (float)(j % 3 + 1);
            int k = (t & 127) >> 1;
            float arg = pos / powf(10000.0f, (float)k / 64.0f);
            g_QP[n * E_DIM + t] = (t & 1) ? cosf(arg) : sinf(arg);
        }
    } else {
        int i = (blk - NTOK - 1) * 256 + t;   // i = e*256 + c
        int e = i >> 8, c = i & 255;
        g_wTk[c * E_DIM + e] = __float2bfloat16(la_wk[i]);
        g_wTv[c * E_DIM + e] = __float2bfloat16(la_wv[i]);
    }
}

// ---------------- kA: Phase A, 256 threads, 32x64 warp tiles, K/V split ----------------
#define ALD 264             // bf16 elems per row (528 B)
#define SA1 0
#define SA2 67584
#define SWR 135168          // 67584 B: W chunks / transpose staging / C staging
#define SMEM_KA 202752

__global__ void __launch_bounds__(256, 1) kA(const float* __restrict__ f_e,
                                             const float* __restrict__ pos) {
    extern __shared__ char sm[];
    __nv_bfloat16* A1 = (__nv_bfloat16*)(sm + SA1);
    __nv_bfloat16* A2 = (__nv_bfloat16*)(sm + SA2);
    __shared__ float psum1[4][64];
    __shared__ float psum2[4][64];

    const int t = threadIdx.x, lane = t & 31, wp = t >> 5;
    const int sblk = blockIdx.x, b = blockIdx.y;
    const int bid = b * 32 + sblk;

    // ---- fused transpose load: f_e [b][e][s] -> A2 [s][e]; A1 = A2 + pos ----
    {
        float* tl = (float*)(sm + SWR) + wp * (32 * 33);
        const float* src = f_e + ((size_t)b * E_DIM + wp * 32) * HW + (size_t)sblk * 128;
#pragma unroll
        for (int ssub = 0; ssub < 4; ssub++) {
            const float* s2 = src + ssub * 32;
#pragma unroll
            for (int i = 0; i < 32; i++) tl[i * 33 + lane] = s2[(size_t)i * HW + lane];
            __syncwarp();
            int sl = ssub * 32 + lane;
            const float* prow = pos + ((size_t)(sblk * 128 + sl) * BS + b) * E_DIM + wp * 32;
            __nv_bfloat16 r1[32], r2[32];
#pragma unroll
            for (int e8 = 0; e8 < 8; e8++) {
                float4 pv = *(const float4*)(prow + e8 * 4);
                float x0 = tl[(e8 * 4 + 0) * 33 + lane];
                float x1 = tl[(e8 * 4 + 1) * 33 + lane];
                float x2 = tl[(e8 * 4 + 2) * 33 + lane];
                float x3 = tl[(e8 * 4 + 3) * 33 + lane];
                r2[e8 * 4 + 0] = __float2bfloat16(x0);
                r2[e8 * 4 + 1] = __float2bfloat16(x1);
                r2[e8 * 4 + 2] = __float2bfloat16(x2);
                r2[e8 * 4 + 3] = __float2bfloat16(x3);
                r1[e8 * 4 + 0] = __float2bfloat16(x0 + pv.x);
                r1[e8 * 4 + 1] = __float2bfloat16(x1 + pv.y);
                r1[e8 * 4 + 2] = __float2bfloat16(x2 + pv.z);
                r1[e8 * 4 + 3] = __float2bfloat16(x3 + pv.w);
            }
            uint4* d1 = (uint4*)(A1 + sl * ALD + wp * 32);
            uint4* d2 = (uint4*)(A2 + sl * ALD + wp * 32);
#pragma unroll
            for (int k = 0; k < 4; k++) {
                d1[k] = ((uint4*)r1)[k];
                d2[k] = ((uint4*)r2)[k];
            }
            __syncwarp();
        }
    }

    __nv_bfloat16* Wk_s = (__nv_bfloat16*)(sm + SWR);            // 64 rows x 528B
    __nv_bfloat16* Wv_s = (__nv_bfloat16*)(sm + SWR + 33792);
    float* st1 = (float*)(sm + SWR);                             // 128 x 66 fp32
    float* st2 = (float*)(sm + SWR + 33792);

    const bool isK = (wp < 4);
    const int m0 = (wp & 3) * 32;
    const __nv_bfloat16* Aw = isK ? A1 : A2;

    for (int ch = 0; ch < 4; ch++) {
        const int c0 = ch * 64;
        __syncthreads();   // prior-phase reads of SWR done
        // ---- load W chunks: 64 c-rows x 256 e each ----
#pragma unroll
        for (int it = 0; it < 8; it++) {
            int idx = it * 256 + t;
            int row = idx >> 5, j = idx & 31;
            *(uint4*)((char*)Wk_s + row * 528 + j * 16) =
                *(const uint4*)(g_wTk + (size_t)(c0 + row) * E_DIM + j * 8);
            *(uint4*)((char*)Wv_s + row * 528 + j * 16) =
                *(const uint4*)(g_wTv + (size_t)(c0 + row) * E_DIM + j * 8);
        }
        __syncthreads();

        // ---- GEMM: warp owns 32 m-rows x 64 n-cols, one matrix ----
        wmma::fragment<wmma::matrix_a, 16, 16, 16, __nv_bfloat16, wmma::row_major> a0, a1;
        wmma::fragment<wmma::matrix_b, 16, 16, 16, __nv_bfloat16, wmma::col_major> bf;
        wmma::fragment<wmma::accumulator, 16, 16, 16, float> acc[2][4];
#pragma unroll
        for (int i = 0; i < 2; i++)
#pragma unroll
            for (int j = 0; j < 4; j++) wmma::fill_fragment(acc[i][j], 0.0f);
        const __nv_bfloat16* Ws = isK ? Wk_s : Wv_s;
#pragma unroll
        for (int kk = 0; kk < 16; kk++) {
            int k = kk * 16;
            wmma::load_matrix_sync(a0, Aw + (size_t)m0 * ALD + k, ALD);
            wmma::load_matrix_sync(a1, Aw + (size_t)(m0 + 16) * ALD + k, ALD);
#pragma unroll
            for (int j = 0; j < 4; j++) {
                wmma::load_matrix_sync(bf, Ws + (size_t)(j * 16) * ALD + k, ALD);
                wmma::mma_sync(acc[0][j], a0, bf, acc[0][j]);
                wmma::mma_sync(acc[1][j], a1, bf, acc[1][j]);
            }
        }
        // K-warps: exp() in registers
        if (isK) {
#pragma unroll
            for (int i = 0; i < 2; i++)
#pragma unroll
                for (int j = 0; j < 4; j++)
#pragma unroll
                    for (int x = 0; x < acc[i][j].num_elements; x++)
                        acc[i][j].x[x] = __expf(acc[i][j].x[x]);
        }
        __syncthreads();   // all W reads done before SWR reuse as staging

        // ---- stage: K-warps -> st1 (=exp(L)), V-warps -> st2 (=VV) ----
        float* st = isK ? st1 : st2;
#pragma unroll
        for (int i = 0; i < 2; i++)
#pragma unroll
            for (int j = 0; j < 4; j++)
                wmma::store_matrix_sync(st + (size_t)(m0 + i * 16) * 66 + j * 16,
                                        acc[i][j], 66, wmma::mem_row_major);
        __syncthreads();

        // ---- columnwise product-sum over 128 rows ----
        {
            int c = t & 63, rseg = t >> 6;
            float a1s = 0.0f, a2s = 0.0f;
#pragma unroll
            for (int r = rseg * 32; r < rseg * 32 + 32; r++) {
                float e = st1[r * 66 + c];
                a1s += e;
                a2s += e * st2[r * 66 + c];
            }
            psum1[rseg][c] = a1s;
            psum2[rseg][c] = a2s;
        }
        __syncthreads();
        if (t < 64) {
            float s1 = psum1[0][t] + psum1[1][t] + psum1[2][t] + psum1[3][t];
            g_Ps1[(size_t)(c0 + t) * NPARTS + bid] = s1;
        } else if (t < 128) {
            int c = t - 64;
            float s2 = psum2[0][c] + psum2[1][c] + psum2[2][c] + psum2[3][c];
            g_Ps2[(size_t)(c0 + c) * NPARTS + bid] = s2;
        }
    }
}

// ---------------- kB: reduce partials -> context ----------------
__global__ void kB(const float* __restrict__ la_bv) {
    int c = blockIdx.x, t = threadIdx.x;
    float s1 = 0.0f, s2 = 0.0f;
#pragma unroll
    for (int j = 0; j < NPARTS / 256; j++) {
        s1 += g_Ps1[(size_t)c * NPARTS + j * 256 + t];
        s2 += g_Ps2[(size_t)c * NPARTS + j * 256 + t];
    }
    s1 = blkSum256(s1);
    s2 = blkSum256(s2);
    if (t == 0) g_ctx[c] = s2 / s1 + la_bv[c];   // la_bk cancels in softmax ratio
}

// ---------------- kC: all 3 refinement steps, one block per token ----------------
// smem floats: KPs 6912 | VPs 6912 | h1 2048 | part 8192 | qpr/f/X/q/y 1280 | scr/al 432
__global__ void __launch_bounds__(1024, 1) kC(
    const float* __restrict__ bq, const float* __restrict__ bo,
    const float* __restrict__ n1g, const float* __restrict__ n1b,
    const float* __restrict__ labq,
    const float* __restrict__ n2g, const float* __restrict__ n2b,
    const float* __restrict__ b1, const float* __restrict__ b2,
    const float* __restrict__ n3g, const float* __restrict__ n3b,
    float* __restrict__ out) {
    extern __shared__ float s[];
    float* KPs = s;
    float* VPs = KPs + NTOK * 256;
    float* h1  = VPs + NTOK * 256;
    float* part= h1 + FFD;
    float* qpr = part + 8192;
    float* f   = qpr + 256;
    float* X   = f + 256;
    float* q   = X + 256;
    float* y   = q + 256;
    float* scr = y + 256;
    float* al  = scr + 8 * NTOK;

    const int n = blockIdx.x, t = threadIdx.x;
    const int g32 = t & 31, d32 = t >> 5;      // 32 col-groups x 32 depth-segs (C=256)

    for (int i = t; i < NTOK * 256; i += 1024) { KPs[i] = g_KP[i]; VPs[i] = g_VP[i]; }
    if (t < 256) { qpr[t] = g_QP[n * 256 + t]; f[t] = g_Fk[n * 256 + t]; }
    __syncthreads();

    for (int step = 0; step < 3; step++) {
        // ======== 1) MHA cross-attention + LN1 ========
        if (t < 256) X[t] = f[t] + qpr[t];
        __syncthreads();
        {   // q = X @ wq (bf16 weights)
            const uint4* w4 = (const uint4*)g_bq;
            float acc[8] = {0, 0, 0, 0, 0, 0, 0, 0};
#pragma unroll
            for (int e = 0; e < 8; e++)
                bf8_fma(w4[(d32 * 8 + e) * 32 + g32], X[d32 * 8 + e], acc);
            float4* pd = (float4*)(part + d32 * 256 + g32 * 8);
            pd[0] = make_float4(acc[0], acc[1], acc[2], acc[3]);
            pd[1] = make_float4(acc[4], acc[5], acc[6], acc[7]);
        }
        __syncthreads();
        if (t < 256) {
            float a = bq[t];
#pragma unroll
            for (int k = 0; k < 32; k++) a += part[k * 256 + t];
            q[t] = a;
        }
        __syncthreads();
        if (t < 8 * NTOK) {
            int h = t / NTOK, sx = t % NTOK;
            float a = 0.0f;
#pragma unroll
            for (int d = 0; d < 32; d++) a += q[h * 32 + d] * KPs[sx * 256 + h * 32 + d];
            scr[t] = a * 0.17677669529663689f;
        }
        __syncthreads();
        if (t < 8) {
            float m = -1e30f;
            for (int sx = 0; sx < NTOK; sx++) m = fmaxf(m, scr[t * NTOK + sx]);
            float su = 0.0f;
            for (int sx = 0; sx < NTOK; sx++) {
                float e = __expf(scr[t * NTOK + sx] - m);
                al[t * NTOK + sx] = e;
                su += e;
            }
            float inv = 1.0f / su;
            for (int sx = 0; sx < NTOK; sx++) al[t * NTOK + sx] *= inv;
        }
        __syncthreads();
        if (t < 256) {
            int h = t >> 5;
            float a = 0.0f;
#pragma unroll
            for (int sx = 0; sx < NTOK; sx++) a += al[h * NTOK + sx] * VPs[sx * 256 + t];
            X[t] = a;
        }
        __syncthreads();
        {   // o = X @ wo
            const uint4* w4 = (const uint4*)g_bo;
            float acc[8] = {0, 0, 0, 0, 0, 0, 0, 0};
#pragma unroll
            for (int e = 0; e < 8; e++)
                bf8_fma(w4[(d32 * 8 + e) * 32 + g32], X[d32 * 8 + e], acc);
            float4* pd = (float4*)(part + d32 * 256 + g32 * 8);
            pd[0] = make_float4(acc[0], acc[1], acc[2], acc[3]);
            pd[1] = make_float4(acc[4], acc[5], acc[6], acc[7]);
        }
        __syncthreads();
        if (t < 256) {
            float a = bo[t];
#pragma unroll
            for (int k = 0; k < 32; k++) a += part[k * 256 + t];
            y[t] = f[t] + a;
        }
        __syncthreads();
        {   // LN1
            float v = (t < 256) ? y[t] : 0.0f;
            float m = bSum(v) * (1.0f / 256.0f);
            float d = (t < 256) ? (y[t] - m) : 0.0f;
            float var = bSum(d * d) * (1.0f / 256.0f);
            if (t < 256) f[t] = d * rsqrtf(var + 1e-5f) * n1g[t] + n1b[t];
        }
        __syncthreads();

        // ======== 2) Linear attention + LN2 ========
        if (t < 256) X[t] = f[t] + qpr[t];
        __syncthreads();
        {
            const uint4* w4 = (const uint4*)g_bl;
            float acc[8] = {0, 0, 0, 0, 0, 0, 0, 0};
#pragma unroll
            for (int e = 0; e < 8; e++)
                bf8_fma(w4[(d32 * 8 + e) * 32 + g32], X[d32 * 8 + e], acc);
            float4* pd = (float4*)(part + d32 * 256 + g32 * 8);
            pd[0] = make_float4(acc[0], acc[1], acc[2], acc[3]);
            pd[1] = make_float4(acc[4], acc[5], acc[6], acc[7]);
        }
        __syncthreads();
        {
            float qa = 0.0f;
            if (t < 256) {
                qa = labq[t];
#pragma unroll
                for (int k = 0; k < 32; k++) qa += part[k * 256 + t];
                qa *= 0.0625f;
            }
            float mv = bMax((t < 256) ? qa : -1e30f);
            float ev = (t < 256) ? __expf(qa - mv) : 0.0f;
            float sv = bSum(ev);
            if (t < 256) y[t] = f[t] + (ev / sv) * g_ctx[t];
        }
        __syncthreads();
        {   // LN2
            float v = (t < 256) ? y[t] : 0.0f;
            float m = bSum(v) * (1.0f / 256.0f);
            float d = (t < 256) ? (y[t] - m) : 0.0f;
            float var = bSum(d * d) * (1.0f / 256.0f);
            if (t < 256) f[t] = d * rsqrtf(var + 1e-5f) * n2g[t] + n2b[t];
        }
        __syncthreads();

        // ======== 3) FFN + LN3 ========
        {   // h1 = gelu(f @ w1 + b1): 256 col-groups x 4 depth-segs (C=2048)
            int g = t & 255, dseg = t >> 8;
            const uint4* w4 = (const uint4*)g_b1;
            float acc[8] = {0, 0, 0, 0, 0, 0, 0, 0};
#pragma unroll 8
            for (int e = 0; e < 64; e++)
                bf8_fma(w4[(dseg * 64 + e) * 256 + g], f[dseg * 64 + e], acc);
            float4* pd = (float4*)(part + dseg * 2048 + g * 8);
            pd[0] = make_float4(acc[0], acc[1], acc[2], acc[3]);
            pd[1] = make_float4(acc[4], acc[5], acc[6], acc[7]);
        }
        __syncthreads();
#pragma unroll
        for (int o = 0; o < 2; o++) {
            int cc = t + o * 1024;
            h1[cc] = gelu_exact(b1[cc] + part[cc] + part[2048 + cc] +
                                part[4096 + cc] + part[6144 + cc]);
        }
        __syncthreads();
        {   // f + h1 @ w2: 32 col-groups x 32 depth-segs (2048 rows)
            const uint4* w4 = (const uint4*)g_b2;
            float acc[8] = {0, 0, 0, 0, 0, 0, 0, 0};
#pragma unroll 8
            for (int j = 0; j < 64; j++)
                bf8_fma(w4[(d32 * 64 + j) * 32 + g32], h1[d32 * 64 + j], acc);
            float4* pd = (float4*)(part + d32 * 256 + g32 * 8);
            pd[0] = make_float4(acc[0], acc[1], acc[2], acc[3]);
            pd[1] = make_float4(acc[4], acc[5], acc[6], acc[7]);
        }
        __syncthreads();
        if (t < 256) {
            float a = b2[t];
#pragma unroll
            for (int k = 0; k < 32; k++) a += part[k * 256 + t];
            y[t] = f[t] + a;
        }
        __syncthreads();
        {   // LN3 + batch-broadcast output
            float v = (t < 256) ? y[t] : 0.0f;
            float m = bSum(v) * (1.0f / 256.0f);
            float d = (t < 256) ? (y[t] - m) : 0.0f;
            float var = bSum(d * d) * (1.0f / 256.0f);
            if (t < 256) {
                float r = d * rsqrtf(var + 1e-5f) * n3g[t] + n3b[t];
                f[t] = r;
                float* o = out + ((size_t)(step * NTOK + n) * BS) * 256 + t;
#pragma unroll
                for (int b = 0; b < BS; b++) o[b * 256] = r;
            }
        }
        __syncthreads();
    }
}

// ---------------- launch ----------------
extern "C" void kernel_launch(void* const* d_in, const int* in_sizes, int n_in,
                              void* d_out, int out_size) {
    const float* f_e      = (const float*)d_in[0];
    const float* pos_emb  = (const float*)d_in[1];
    const float* shape_map= (const float*)d_in[3];
    const float* mha_wq   = (const float*)d_in[4];
    const float* mha_bq   = (const float*)d_in[5];
    const float* mha_wk   = (const float*)d_in[6];
    const float* mha_bk   = (const float*)d_in[7];
    const float* mha_wv   = (const float*)d_in[8];
    const float* mha_bv   = (const float*)d_in[9];
    const float* mha_wo   = (const float*)d_in[10];
    const float* mha_bo   = (const float*)d_in[11];
    const float* la_wq    = (const float*)d_in[12];
    const float* la_bq    = (const float*)d_in[13];
    const float* la_wk    = (const float*)d_in[14];
    const float* la_wv    = (const float*)d_in[16];
    const float* la_bv    = (const float*)d_in[17];
    const float* ff_w1    = (const float*)d_in[18];
    const float* ff_b1    = (const float*)d_in[19];
    const float* ff_w2    = (const float*)d_in[20];
    const float* ff_b2    = (const float*)d_in[21];
    const float* n1_g     = (const float*)d_in[22];
    const float* n1_b     = (const float*)d_in[23];
    const float* n2_g     = (const float*)d_in[24];
    const float* n2_b     = (const float*)d_in[25];
    const float* n3_g     = (const float*)d_in[26];
    const float* n3_b     = (const float*)d_in[27];
    float* out = (float*)d_out;

    cudaFuncSetAttribute(kA, cudaFuncAttributeMaxDynamicSharedMemorySize, SMEM_KA);
    cudaFuncSetAttribute(kC, cudaFuncAttributeMaxDynamicSharedMemorySize, 120 * 1024);
    const int kc_smem = (2 * NTOK * 256 + FFD + 8192 + 5 * 256 + 2 * 8 * NTOK) * 4;

    kConv<<<4864, 256>>>(mha_wq, mha_wo, la_wq, ff_w1, ff_w2);
    kPrep<<<NTOK + 1 + 256, 256>>>(shape_map, mha_wk, mha_bk, mha_wv, mha_bv, la_wk, la_wv);
    kA<<<dim3(32, BS), 256, SMEM_KA>>>(f_e, pos_emb);
    kB<<<E_DIM, 256>>>(la_bv);
    kC<<<NTOK, 1024, kc_smem>>>(mha_bq, mha_bo, n1_g, n1_b, la_bq, n2_g, n2_b,
                                ff_b1, ff_b2, n3_g, n3_b, out);
}